// round 3
// baseline (speedup 1.0000x reference)
#include <cuda_runtime.h>

#define D 256
#define P 8
#define B_GR 128
#define N_NODES 50000
#define N_EDGES 300000
#define TPB 32
#define NBLK_EDGE ((N_EDGES + TPB - 1) / TPB)
#define NBLK_NODE ((N_NODES + TPB - 1) / TPB)

typedef unsigned long long ull;

// Packed layouts: [kpair][d][2] where [..][0]=W[2kp][d], [..][1]=W[2kp+1][d]
__device__ __align__(16) float g_WpP[P * D * D];      // per-p packed node weights
__device__ __align__(16) float g_WeP[D * D];          // packed edge weights
__device__ __align__(16) float g_WeffP[B_GR * D * D]; // per-graph packed effective weights
__device__ float g_state_logits[N_NODES];
__device__ float g_rel_logits[N_NODES];

__device__ __forceinline__ void fma2(ull& acc, ull a, ull b) {
    asm("fma.rn.f32x2 %0, %1, %2, %0;" : "+l"(acc) : "l"(a), "l"(b));
}
__device__ __forceinline__ float hsum2(ull v) {
    float lo, hi;
    asm("mov.b64 {%0, %1}, %2;" : "=f"(lo), "=f"(hi) : "l"(v));
    return lo + hi;
}
__device__ __forceinline__ float elu1(float x) { return x > 0.f ? x : expm1f(x); }

// ---------- prep: transpose + kpair-interleave ----------
// dest idx for (d_out, k): (k>>1)*(2*D) + 2*d + (k&1)
__global__ void prep_kernel(const float* __restrict__ Wnp, const float* __restrict__ We) {
    int tid = blockIdx.x * blockDim.x + threadIdx.x;
    if (tid < P * D * D) {
        int p = tid >> 16;
        int rem = tid & 0xFFFF;
        int d = rem >> 8;
        int k = rem & 0xFF;
        g_WpP[p * (D * D) + (k >> 1) * (2 * D) + 2 * d + (k & 1)] = Wnp[tid];
    } else if (tid < P * D * D + D * D) {
        int r = tid - P * D * D;
        int d = r >> 8;
        int k = r & 0xFF;
        g_WeP[(k >> 1) * (2 * D) + 2 * d + (k & 1)] = We[r];
    }
}

// ---------- W_effP[b] = sum_p sim[b][p] * WpP[p]  (layout-agnostic elementwise) ----------
__global__ void __launch_bounds__(256) weff_kernel(const float* __restrict__ sim) {
    __shared__ float wpt_s[P][256];
    __shared__ float sim_s[B_GR * P];
    const int t = threadIdx.x;
    const int base = blockIdx.x * 256;
#pragma unroll
    for (int p = 0; p < P; p++) wpt_s[p][t] = g_WpP[p * (D * D) + base + t];
    for (int i = t; i < B_GR * P; i += 256) sim_s[i] = sim[i];
    __syncthreads();
    for (int b = 0; b < B_GR; b++) {
        float a = 0.f;
#pragma unroll
        for (int p = 0; p < P; p++) a = fmaf(sim_s[b * P + p], wpt_s[p][t], a);
        g_WeffP[(size_t)b * (D * D) + base + t] = a;
    }
}

__global__ void zero_kernel() {
    int i = blockIdx.x * blockDim.x + threadIdx.x;
    if (i < N_NODES) g_rel_logits[i] = 0.f;
}

// ---------- fused node+edge GEMV-scoring kernel ----------
// 256 threads = 64 d-groups (4 d's each) x 4 row-groups (8 rows each); 32-row tiles.
// acc[j][dd] is f32x2 = (sum over even k, sum over odd k) for row j, dim d0+dd.
__global__ void __launch_bounds__(256, 2) main_kernel(
    const float* __restrict__ node_attrs, const int* __restrict__ node_indices,
    const float* __restrict__ edge_attrs, const int* __restrict__ edge_batch,
    const int* __restrict__ src, const int* __restrict__ dst,
    const float* __restrict__ distribution, const float* __restrict__ instr,
    const float* __restrict__ w_node, const float* __restrict__ w_rel) {
    __shared__ __align__(16) float attr_s[TPB][D];
    __shared__ int b_s[TPB];
    __shared__ float red[TPB][2];

    const int t = threadIdx.x;
    const int dg = t & 63;
    const int rg = t >> 6;
    const int d0 = dg * 4;
    const int rowbase = rg * 8;

    const bool isEdge = blockIdx.x < NBLK_EDGE;
    const int i0 = isEdge ? blockIdx.x * TPB : (blockIdx.x - NBLK_EDGE) * TPB;
    const int limit = isEdge ? N_EDGES : N_NODES;
    const int cnt = min(TPB, limit - i0);
    const float* __restrict__ gattr = isEdge ? edge_attrs : node_attrs;

    // stage attr tile (zero-padded)
    {
        const float4* ga4 = (const float4*)(gattr + (size_t)i0 * D);
        float4* as4 = (float4*)attr_s;
        const int nv = cnt * (D / 4);
        for (int idx = t; idx < TPB * (D / 4); idx += 256)
            as4[idx] = (idx < nv) ? __ldg(ga4 + idx) : make_float4(0.f, 0.f, 0.f, 0.f);
    }
    if (t < TPB) b_s[t] = (t < cnt) ? (isEdge ? edge_batch[i0 + t] : node_indices[i0 + t]) : -1;
    __syncthreads();

    ull acc[8][4];
#pragma unroll
    for (int j = 0; j < 8; j++)
#pragma unroll
        for (int dd = 0; dd < 4; dd++) acc[j][dd] = 0ull;

    const float* WbaseP;
    bool fast;
    if (isEdge) {
        WbaseP = g_WeP;
        fast = true;
    } else {
        int bfirst = b_s[0];
        fast = (cnt == TPB) && (bfirst == b_s[TPB - 1]);
        WbaseP = g_WeffP + (size_t)bfirst * (D * D);
    }

    if (fast) {
        const float* attrRow = &attr_s[rowbase][0];
        // float2 element index: kp*D + d
        const float2* __restrict__ Wp = (const float2*)WbaseP + d0;
#pragma unroll 2
        for (int kp = 0; kp < D / 2; kp += 2) {
            ulonglong2 w0 = __ldg((const ulonglong2*)(Wp + (size_t)kp * D));        // kp: d0,d0+1
            ulonglong2 w1 = __ldg((const ulonglong2*)(Wp + (size_t)kp * D + 2));    // kp: d0+2,d0+3
            ulonglong2 w2 = __ldg((const ulonglong2*)(Wp + (size_t)(kp + 1) * D));  // kp+1
            ulonglong2 w3 = __ldg((const ulonglong2*)(Wp + (size_t)(kp + 1) * D + 2));
#pragma unroll
            for (int j = 0; j < 8; j++) {
                ulonglong2 au = *(const ulonglong2*)(attrRow + j * D + 2 * kp);  // k..k+3
                fma2(acc[j][0], au.x, w0.x);
                fma2(acc[j][1], au.x, w0.y);
                fma2(acc[j][2], au.x, w1.x);
                fma2(acc[j][3], au.x, w1.y);
                fma2(acc[j][0], au.y, w2.x);
                fma2(acc[j][1], au.y, w2.y);
                fma2(acc[j][2], au.y, w3.x);
                fma2(acc[j][3], au.y, w3.y);
            }
        }
    } else {
        // graph boundary inside tile (rare): per-row W
#pragma unroll 1
        for (int j = 0; j < 8; j++) {
            int row = rowbase + j;
            if (row >= cnt) break;
            const float2* __restrict__ Wp =
                (const float2*)(g_WeffP + (size_t)b_s[row] * (D * D)) + d0;
            ull c0 = 0ull, c1 = 0ull, c2 = 0ull, c3 = 0ull;
            for (int kp = 0; kp < D / 2; kp++) {
                ulonglong2 w0 = __ldg((const ulonglong2*)(Wp + (size_t)kp * D));
                ulonglong2 w1 = __ldg((const ulonglong2*)(Wp + (size_t)kp * D + 2));
                ull a = *(const ull*)(&attr_s[row][2 * kp]);
                fma2(c0, a, w0.x);
                fma2(c1, a, w0.y);
                fma2(c2, a, w1.x);
                fma2(c3, a, w1.y);
            }
            acc[j][0] = c0;
            acc[j][1] = c1;
            acc[j][2] = c2;
            acc[j][3] = c3;
        }
    }

    // epilogue: x_d = hsum(acc); v = sum_d w[d]*elu(instr[b][d]*x_d); warp-reduce per row
    const float* wvec = isEdge ? w_rel : w_node;
    const float4 wr4 = __ldg((const float4*)(wvec + d0));
    const int half = (t >> 5) & 1;
#pragma unroll
    for (int j = 0; j < 8; j++) {
        int row = rowbase + j;
        float local = 0.f;
        if (row < cnt) {
            int b = b_s[row];
            float4 ins = __ldg((const float4*)(instr + b * D + d0));
            float x0 = hsum2(acc[j][0]);
            float x1 = hsum2(acc[j][1]);
            float x2 = hsum2(acc[j][2]);
            float x3 = hsum2(acc[j][3]);
            local = wr4.x * elu1(ins.x * x0) + wr4.y * elu1(ins.y * x1) +
                    wr4.z * elu1(ins.z * x2) + wr4.w * elu1(ins.w * x3);
        }
#pragma unroll
        for (int o = 16; o > 0; o >>= 1) local += __shfl_down_sync(0xFFFFFFFFu, local, o);
        if ((t & 31) == 0) red[row][half] = local;
    }
    __syncthreads();
    if (t < cnt) {
        float v = red[t][0] + red[t][1];
        int g = i0 + t;
        if (isEdge) {
            atomicAdd(&g_rel_logits[dst[g]], distribution[src[g]] * v);
        } else {
            g_state_logits[g] = v;
        }
    }
}

// ---------- segment softmax + combine ----------
__device__ __forceinline__ int lower_bound_dev(const int* __restrict__ a, int n, int key) {
    int lo = 0, hi = n;
    while (lo < hi) {
        int mid = (lo + hi) >> 1;
        if (a[mid] < key) lo = mid + 1; else hi = mid;
    }
    return lo;
}

__global__ void __launch_bounds__(256) softmax_kernel(const int* __restrict__ nidx,
                                                      const float* __restrict__ rel_sim,
                                                      float* __restrict__ out) {
    const int b = blockIdx.x;
    const int t = threadIdx.x;
    __shared__ float sh[256];
    __shared__ int bounds[2];
    if (t == 0) {
        bounds[0] = lower_bound_dev(nidx, N_NODES, b);
        bounds[1] = lower_bound_dev(nidx, N_NODES, b + 1);
    }
    __syncthreads();
    const int lo = bounds[0], hi = bounds[1];
    if (hi <= lo) return;

    float m1 = -1e30f, m2 = -1e30f;
    for (int i = lo + t; i < hi; i += 256) {
        m1 = fmaxf(m1, g_state_logits[i]);
        m2 = fmaxf(m2, g_rel_logits[i]);
    }
    sh[t] = m1; __syncthreads();
    for (int o = 128; o > 0; o >>= 1) { if (t < o) sh[t] = fmaxf(sh[t], sh[t + o]); __syncthreads(); }
    m1 = sh[0]; __syncthreads();
    sh[t] = m2; __syncthreads();
    for (int o = 128; o > 0; o >>= 1) { if (t < o) sh[t] = fmaxf(sh[t], sh[t + o]); __syncthreads(); }
    m2 = sh[0]; __syncthreads();

    float s1 = 0.f, s2 = 0.f;
    for (int i = lo + t; i < hi; i += 256) {
        s1 += expf(g_state_logits[i] - m1);
        s2 += expf(g_rel_logits[i] - m2);
    }
    sh[t] = s1; __syncthreads();
    for (int o = 128; o > 0; o >>= 1) { if (t < o) sh[t] += sh[t + o]; __syncthreads(); }
    s1 = sh[0]; __syncthreads();
    sh[t] = s2; __syncthreads();
    for (int o = 128; o > 0; o >>= 1) { if (t < o) sh[t] += sh[t + o]; __syncthreads(); }
    s2 = sh[0]; __syncthreads();

    const float r = rel_sim[b];
    const float inv1 = 1.f / s1, inv2 = 1.f / s2;
    for (int i = lo + t; i < hi; i += 256) {
        float ns = expf(g_state_logits[i] - m1) * inv1;
        float nr = expf(g_rel_logits[i] - m2) * inv2;
        out[i] = r * nr + (1.f - r) * ns;
    }
}

extern "C" void kernel_launch(void* const* d_in, const int* in_sizes, int n_in,
                              void* d_out, int out_size) {
    const float* instr        = (const float*)d_in[0];
    const float* distribution = (const float*)d_in[1];
    const float* sim          = (const float*)d_in[2];
    const float* rel_sim      = (const float*)d_in[3];
    const float* node_attrs   = (const float*)d_in[4];
    const float* edge_attrs   = (const float*)d_in[5];
    const float* Wnp          = (const float*)d_in[6];
    const float* We           = (const float*)d_in[7];
    const float* w_node       = (const float*)d_in[8];
    const float* w_rel        = (const float*)d_in[9];
    const int*   node_indices = (const int*)d_in[10];
    const int*   edge_batch   = (const int*)d_in[11];
    const int*   ei           = (const int*)d_in[12];
    float* out = (float*)d_out;

    prep_kernel<<<(P * D * D + D * D + 255) / 256, 256>>>(Wnp, We);
    weff_kernel<<<(D * D) / 256, 256>>>(sim);
    zero_kernel<<<(N_NODES + 255) / 256, 256>>>();
    main_kernel<<<NBLK_EDGE + NBLK_NODE, 256>>>(node_attrs, node_indices, edge_attrs,
                                                edge_batch, ei, ei + N_EDGES, distribution,
                                                instr, w_node, w_rel);
    softmax_kernel<<<B_GR, 256>>>(node_indices, rel_sim, out);
}

// round 5
// speedup vs baseline: 2.2129x; 2.2129x over previous
#include <cuda_runtime.h>
#include <cuda_bf16.h>
#include <cstdint>

#define D 256
#define P 8
#define B_GR 128
#define N_NODES 50000
#define N_EDGES 300000
#define NHB 148
#define MAX_TILES 3072
#define KC 32
#define NCHUNK 8
#define W_CHUNK_ELEMS (256 * KC)   // 8192 bf16 per chunk (per hi or lo)
#define WSP_HALF (129 * NCHUNK * W_CHUNK_ELEMS)

// dynamic smem byte offsets
#define OFF_INSTR 0
#define OFF_WVEC 1024
#define OFF_RED 2048               // 128 rows x 8 floats
#define OFF_A 6144                 // 2 buf x (hi,lo) x 128 x 40 bf16 (stride 80B)
#define A_BUF_BYTES 20480          // hi+lo for one buffer
#define A_HL_BYTES 10240
#define OFF_W 47104                // 2 buf x (hi,lo) x 256 x 40 bf16
#define W_BUF_BYTES 40960
#define W_HL_BYTES 20480
#define SMEM_NEED 129024

// ---------------- device globals ----------------
__device__ __align__(256) __nv_bfloat16 g_Wsp[2 * WSP_HALF]; // [hi/lo][widx][chunk][n=256][k=32]
__device__ float g_state_logits[N_NODES];
__device__ float g_rel_logits[N_NODES];
__device__ int g_eperm[N_EDGES];
__device__ int g_edst[N_EDGES];
__device__ float g_ecoef[N_EDGES];
__device__ int g_bintotal[B_GR];
__device__ int g_binstart[B_GR + 1];
__device__ int g_blockhist[NHB * B_GR];
__device__ int g_blockbase[NHB * B_GR];
__device__ int4 g_tiles[MAX_TILES]; // {widx, b, start, cnt}
__device__ int g_ntiles;

// ---------------- helpers ----------------
__device__ __forceinline__ uint32_t smem_u32(const void* p) {
    uint32_t a;
    asm("{ .reg .u64 t; cvta.to.shared.u64 t, %1; cvt.u32.u64 %0, t; }" : "=r"(a) : "l"(p));
    return a;
}
__device__ __forceinline__ void ldsm4(uint32_t* r, uint32_t addr) {
    asm volatile("ldmatrix.sync.aligned.m8n8.x4.shared.b16 {%0,%1,%2,%3}, [%4];"
                 : "=r"(r[0]), "=r"(r[1]), "=r"(r[2]), "=r"(r[3]) : "r"(addr));
}
__device__ __forceinline__ void mma16816(float* c, const uint32_t* a, uint32_t b0, uint32_t b1) {
    asm volatile(
        "mma.sync.aligned.m16n8k16.row.col.f32.bf16.bf16.f32 "
        "{%0,%1,%2,%3}, {%4,%5,%6,%7}, {%8,%9}, {%0,%1,%2,%3};"
        : "+f"(c[0]), "+f"(c[1]), "+f"(c[2]), "+f"(c[3])
        : "r"(a[0]), "r"(a[1]), "r"(a[2]), "r"(a[3]), "r"(b0), "r"(b1));
}
__device__ __forceinline__ void cpasync16(uint32_t saddr, const void* gaddr) {
    asm volatile("cp.async.cg.shared.global [%0], [%1], 16;" :: "r"(saddr), "l"(gaddr) : "memory");
}
__device__ __forceinline__ void cp_commit() { asm volatile("cp.async.commit_group;" ::: "memory"); }
__device__ __forceinline__ void cp_wait_all() { asm volatile("cp.async.wait_group 0;" ::: "memory"); }
__device__ __forceinline__ float elu1(float x) { return x > 0.f ? x : expm1f(x); }

// ---------------- prep kernels ----------------
__global__ void zero_kernel() {
    int i = blockIdx.x * blockDim.x + threadIdx.x;
    if (i < N_NODES) g_rel_logits[i] = 0.f;
    if (i < B_GR) g_bintotal[i] = 0;
    if (i < NHB * B_GR) g_blockhist[i] = 0;
}

__global__ void __launch_bounds__(256) hist_kernel(const int* __restrict__ eb) {
    __shared__ int h[B_GR];
    int t = threadIdx.x;
    if (t < B_GR) h[t] = 0;
    __syncthreads();
    for (int e = blockIdx.x * 256 + t; e < N_EDGES; e += gridDim.x * 256)
        atomicAdd(&h[eb[e]], 1);
    __syncthreads();
    if (t < B_GR) {
        g_blockhist[blockIdx.x * B_GR + t] = h[t];
        atomicAdd(&g_bintotal[t], h[t]);
    }
}

__global__ void scan_kernel() {
    __shared__ int starts[B_GR + 1];
    int b = threadIdx.x;
    if (b == 0) {
        int run = 0;
        for (int i = 0; i < B_GR; i++) { starts[i] = run; run += g_bintotal[i]; }
        starts[B_GR] = run;
        for (int i = 0; i <= B_GR; i++) g_binstart[i] = starts[i];
    }
    __syncthreads();
    if (b < B_GR) {
        int run = starts[b];
        for (int blk = 0; blk < NHB; blk++) {
            g_blockbase[blk * B_GR + b] = run;
            run += g_blockhist[blk * B_GR + b];
        }
    }
}

__global__ void __launch_bounds__(256) scatter_kernel(const int* __restrict__ eb,
                                                      const int* __restrict__ src,
                                                      const int* __restrict__ dst,
                                                      const float* __restrict__ dist) {
    __shared__ int cur[B_GR];
    int t = threadIdx.x;
    if (t < B_GR) cur[t] = g_blockbase[blockIdx.x * B_GR + t];
    __syncthreads();
    for (int e = blockIdx.x * 256 + t; e < N_EDGES; e += gridDim.x * 256) {
        int b = eb[e];
        int pos = atomicAdd(&cur[b], 1);
        g_eperm[pos] = e;
        g_edst[pos] = dst[e];
        g_ecoef[pos] = dist[src[e]];
    }
}

// split fp32 -> (hi,lo) bf16, chunk-blocked [widx][chunk][n][k32]
__device__ __forceinline__ void store_split(int widx, int n, int k, float v) {
    __nv_bfloat16 h = __float2bfloat16_rn(v);
    __nv_bfloat16 l = __float2bfloat16_rn(v - __bfloat162float(h));
    int chunk = k >> 5, kk = k & 31;
    size_t idx = ((size_t)(widx * NCHUNK + chunk) * 256 + n) * 32 + kk;
    g_Wsp[idx] = h;
    g_Wsp[idx + WSP_HALF] = l;
}

__global__ void __launch_bounds__(256) wsplit_kernel(const float* __restrict__ Wnp,
                                                     const float* __restrict__ We,
                                                     const float* __restrict__ sim) {
    __shared__ float sim_s[B_GR * P];
    int t = threadIdx.x;
    for (int i = t; i < B_GR * P; i += 256) sim_s[i] = sim[i];
    __syncthreads();
    int pos = blockIdx.x * 256 + t;  // (n,k): n=pos>>8, k=pos&255; W layouts are [n][k] already
    int n = pos >> 8, k = pos & 255;
    store_split(128, n, k, We[pos]);
    float wp[P];
#pragma unroll
    for (int p = 0; p < P; p++) wp[p] = Wnp[p * (D * D) + pos];
    for (int b = 0; b < B_GR; b++) {
        float a = 0.f;
#pragma unroll
        for (int p = 0; p < P; p++) a = fmaf(sim_s[b * P + p], wp[p], a);
        store_split(b, n, k, a);
    }
}

__device__ __forceinline__ int lower_bound_dev(const int* __restrict__ a, int n, int key) {
    int lo = 0, hi = n;
    while (lo < hi) {
        int mid = (lo + hi) >> 1;
        if (a[mid] < key) lo = mid + 1; else hi = mid;
    }
    return lo;
}

__global__ void plan_kernel(const int* __restrict__ nidx) {
    __shared__ int cnts[B_GR];
    __shared__ int starts[B_GR];
    int b = threadIdx.x;
    int elo = g_binstart[b], ecnt = g_binstart[b + 1] - elo;
    int nlo = lower_bound_dev(nidx, N_NODES, b);
    int ncnt = lower_bound_dev(nidx, N_NODES, b + 1) - nlo;
    int et = (ecnt + 127) >> 7, nt = (ncnt + 127) >> 7;
    cnts[b] = et + nt;
    __syncthreads();
    if (b == 0) {
        int run = 0;
        for (int i = 0; i < B_GR; i++) { starts[i] = run; run += cnts[i]; }
        g_ntiles = run;
    }
    __syncthreads();
    int idx = starts[b];
    for (int t = 0; t < et; t++)
        g_tiles[idx++] = make_int4(128, b, elo + t * 128, min(128, ecnt - t * 128));
    for (int t = 0; t < nt; t++)
        g_tiles[idx++] = make_int4(b, b, nlo + t * 128, min(128, ncnt - t * 128));
}

// ---------------- main HMMA kernel ----------------
// 512 threads, 16 warps = 2 m-groups (64 rows) x 8 n-groups (32 cols).
__global__ void __launch_bounds__(512) main_kernel(const float* __restrict__ node_attrs,
                                                   const float* __restrict__ edge_attrs,
                                                   const float* __restrict__ instr,
                                                   const float* __restrict__ w_node,
                                                   const float* __restrict__ w_rel) {
    extern __shared__ char smem[];
    if (blockIdx.x >= g_ntiles) return;
    const int4 ti = g_tiles[blockIdx.x];
    const bool isEdge = (ti.x == 128);
    const int tid = threadIdx.x;
    const int lane = tid & 31;
    const int wid = tid >> 5;
    const int mbase = (wid & 1) * 64;
    const int ngrp = wid >> 1;
    const int nbase = ngrp * 32;

    const uint32_t sb = smem_u32(smem);
    float* instr_s = (float*)(smem + OFF_INSTR);
    float* wvec_s = (float*)(smem + OFF_WVEC);
    float* red = (float*)(smem + OFF_RED);

    if (tid < 256) {
        instr_s[tid] = instr[ti.y * D + tid];
        wvec_s[tid] = (isEdge ? w_rel : w_node)[tid];
    }

    // A row assignment: thread handles row (tid>>2), k-segment (tid&3)*8 per chunk
    const int arow = tid >> 2;
    const int kseg = (tid & 3) * 8;
    const bool valid = arow < ti.w;
    const float* rowsrc = node_attrs;  // dummy
    if (valid)
        rowsrc = isEdge ? edge_attrs + (size_t)g_eperm[ti.z + arow] * D
                        : node_attrs + (size_t)(ti.z + arow) * D;

    const __nv_bfloat16* wh = g_Wsp + (size_t)ti.x * NCHUNK * W_CHUNK_ELEMS;
    const __nv_bfloat16* wl = wh + (size_t)WSP_HALF;

    float acc[4][4][4];
#pragma unroll
    for (int a = 0; a < 4; a++)
#pragma unroll
        for (int b = 0; b < 4; b++)
#pragma unroll
            for (int c = 0; c < 4; c++) acc[a][b][c] = 0.f;

    // ---- helpers as macros over locals ----
    float4 va, vb;
#define ISSUE_W(c, buf)                                                            \
    do {                                                                           \
        uint32_t wbb = sb + OFF_W + (buf) * W_BUF_BYTES;                           \
        for (int s = tid; s < 1024; s += 512) {                                    \
            int n_ = s >> 2, ks_ = s & 3;                                          \
            uint32_t d_ = wbb + n_ * 80 + ks_ * 16;                                \
            size_t g_ = (size_t)(c) * W_CHUNK_ELEMS + n_ * 32 + ks_ * 8;           \
            cpasync16(d_, wh + g_);                                                \
            cpasync16(d_ + W_HL_BYTES, wl + g_);                                   \
        }                                                                          \
        cp_commit();                                                               \
    } while (0)

#define LDG_A(c)                                                                   \
    do {                                                                           \
        if (valid) {                                                               \
            const float4* p_ = (const float4*)(rowsrc + (c) * KC + kseg);          \
            va = __ldg(p_);                                                        \
            vb = __ldg(p_ + 1);                                                    \
        } else {                                                                   \
            va = make_float4(0.f, 0.f, 0.f, 0.f);                                  \
            vb = va;                                                               \
        }                                                                          \
    } while (0)

#define STS_A(buf)                                                                 \
    do {                                                                           \
        __nv_bfloat162 h0 = __floats2bfloat162_rn(va.x, va.y);                     \
        __nv_bfloat162 h1 = __floats2bfloat162_rn(va.z, va.w);                     \
        __nv_bfloat162 h2 = __floats2bfloat162_rn(vb.x, vb.y);                     \
        __nv_bfloat162 h3 = __floats2bfloat162_rn(vb.z, vb.w);                     \
        __nv_bfloat162 l0 = __floats2bfloat162_rn(va.x - __low2float(h0), va.y - __high2float(h0)); \
        __nv_bfloat162 l1 = __floats2bfloat162_rn(va.z - __low2float(h1), va.w - __high2float(h1)); \
        __nv_bfloat162 l2 = __floats2bfloat162_rn(vb.x - __low2float(h2), vb.y - __high2float(h2)); \
        __nv_bfloat162 l3 = __floats2bfloat162_rn(vb.z - __low2float(h3), vb.w - __high2float(h3)); \
        char* ab_ = smem + OFF_A + (buf) * A_BUF_BYTES + arow * 80 + kseg * 2;     \
        uint4 hv_, lv_;                                                            \
        hv_.x = *(uint32_t*)&h0; hv_.y = *(uint32_t*)&h1;                          \
        hv_.z = *(uint32_t*)&h2; hv_.w = *(uint32_t*)&h3;                          \
        lv_.x = *(uint32_t*)&l0; lv_.y = *(uint32_t*)&l1;                          \
        lv_.z = *(uint32_t*)&l2; lv_.w = *(uint32_t*)&l3;                          \
        *(uint4*)ab_ = hv_;                                                        \
        *(uint4*)(ab_ + A_HL_BYTES) = lv_;                                         \
    } while (0)

    // prologue
    ISSUE_W(0, 0);
    LDG_A(0);
    STS_A(0);

#pragma unroll 1
    for (int c = 0; c < NCHUNK; c++) {
        cp_wait_all();
        __syncthreads();
        const int buf = c & 1;
        if (c + 1 < NCHUNK) {
            ISSUE_W(c + 1, buf ^ 1);
            LDG_A(c + 1);
        }
        // mma on chunk c
        const uint32_t abase = sb + OFF_A + buf * A_BUF_BYTES;
        const uint32_t wbase = sb + OFF_W + buf * W_BUF_BYTES;
#pragma unroll
        for (int ks = 0; ks < 2; ks++) {
            const int k0 = ks * 16;
            uint32_t ah[4][4], al[4][4];
#pragma unroll
            for (int mi = 0; mi < 4; mi++) {
                uint32_t ra = abase + (mbase + mi * 16 + (lane & 15)) * 80 + k0 * 2 + ((lane >> 4) * 16);
                ldsm4(ah[mi], ra);
                ldsm4(al[mi], ra + A_HL_BYTES);
            }
#pragma unroll
            for (int nip = 0; nip < 2; nip++) {
                const int n0 = nbase + nip * 16;
                uint32_t rb = wbase + (n0 + ((lane >> 4) << 3) + (lane & 7)) * 80 + k0 * 2 +
                              (((lane >> 3) & 1) * 16);
                uint32_t bh[4], bl[4];
                ldsm4(bh, rb);
                ldsm4(bl, rb + W_HL_BYTES);
#pragma unroll
                for (int mi = 0; mi < 4; mi++) {
                    mma16816(acc[mi][nip * 2 + 0], ah[mi], bh[0], bh[1]);
                    mma16816(acc[mi][nip * 2 + 1], ah[mi], bh[2], bh[3]);
                    mma16816(acc[mi][nip * 2 + 0], ah[mi], bl[0], bl[1]);
                    mma16816(acc[mi][nip * 2 + 1], ah[mi], bl[2], bl[3]);
                    mma16816(acc[mi][nip * 2 + 0], al[mi], bh[0], bh[1]);
                    mma16816(acc[mi][nip * 2 + 1], al[mi], bh[2], bh[3]);
                }
            }
        }
        if (c + 1 < NCHUNK) STS_A(buf ^ 1);
    }

    // ---- epilogue: per-row v = sum_d w[d]*elu(instr[d]*x[d]) ----
#pragma unroll
    for (int mi = 0; mi < 4; mi++) {
        float pr0 = 0.f, pr1 = 0.f;
#pragma unroll
        for (int ni = 0; ni < 4; ni++) {
            int c0 = nbase + ni * 8 + (lane & 3) * 2;
            float w0 = wvec_s[c0], w1 = wvec_s[c0 + 1];
            float i0 = instr_s[c0], i1 = instr_s[c0 + 1];
            pr0 += w0 * elu1(i0 * acc[mi][ni][0]) + w1 * elu1(i1 * acc[mi][ni][1]);
            pr1 += w0 * elu1(i0 * acc[mi][ni][2]) + w1 * elu1(i1 * acc[mi][ni][3]);
        }
        pr0 += __shfl_xor_sync(0xFFFFFFFFu, pr0, 1);
        pr0 += __shfl_xor_sync(0xFFFFFFFFu, pr0, 2);
        pr1 += __shfl_xor_sync(0xFFFFFFFFu, pr1, 1);
        pr1 += __shfl_xor_sync(0xFFFFFFFFu, pr1, 2);
        if ((lane & 3) == 0) {
            int row = mbase + mi * 16 + (lane >> 2);
            red[row * 8 + ngrp] = pr0;
            red[(row + 8) * 8 + ngrp] = pr1;
        }
    }
    __syncthreads();
    if (tid < 128 && tid < ti.w) {
        float v = 0.f;
#pragma unroll
        for (int g = 0; g < 8; g++) v += red[tid * 8 + g];
        int gl = ti.z + tid;
        if (isEdge) atomicAdd(&g_rel_logits[g_edst[gl]], g_ecoef[gl] * v);
        else g_state_logits[gl] = v;
    }
#undef ISSUE_W
#undef LDG_A
#undef STS_A
}

// ---------------- segment softmax + combine ----------------
__global__ void __launch_bounds__(256) softmax_kernel(const int* __restrict__ nidx,
                                                      const float* __restrict__ rel_sim,
                                                      float* __restrict__ out) {
    const int b = blockIdx.x;
    const int t = threadIdx.x;
    __shared__ float sh[256];
    __shared__ int bounds[2];
    if (t == 0) {
        bounds[0] = lower_bound_dev(nidx, N_NODES, b);
        bounds[1] = lower_bound_dev(nidx, N_NODES, b + 1);
    }
    __syncthreads();
    const int lo = bounds[0], hi = bounds[1];
    if (hi <= lo) return;

    float m1 = -1e30f, m2 = -1e30f;
    for (int i = lo + t; i < hi; i += 256) {
        m1 = fmaxf(m1, g_state_logits[i]);
        m2 = fmaxf(m2, g_rel_logits[i]);
    }
    sh[t] = m1; __syncthreads();
    for (int o = 128; o > 0; o >>= 1) { if (t < o) sh[t] = fmaxf(sh[t], sh[t + o]); __syncthreads(); }
    m1 = sh[0]; __syncthreads();
    sh[t] = m2; __syncthreads();
    for (int o = 128; o > 0; o >>= 1) { if (t < o) sh[t] = fmaxf(sh[t], sh[t + o]); __syncthreads(); }
    m2 = sh[0]; __syncthreads();

    float s1 = 0.f, s2 = 0.f;
    for (int i = lo + t; i < hi; i += 256) {
        s1 += expf(g_state_logits[i] - m1);
        s2 += expf(g_rel_logits[i] - m2);
    }
    sh[t] = s1; __syncthreads();
    for (int o = 128; o > 0; o >>= 1) { if (t < o) sh[t] += sh[t + o]; __syncthreads(); }
    s1 = sh[0]; __syncthreads();
    sh[t] = s2; __syncthreads();
    for (int o = 128; o > 0; o >>= 1) { if (t < o) sh[t] += sh[t + o]; __syncthreads(); }
    s2 = sh[0]; __syncthreads();

    const float r = rel_sim[b];
    const float inv1 = 1.f / s1, inv2 = 1.f / s2;
    for (int i = lo + t; i < hi; i += 256) {
        float ns = expf(g_state_logits[i] - m1) * inv1;
        float nr = expf(g_rel_logits[i] - m2) * inv2;
        out[i] = r * nr + (1.f - r) * ns;
    }
}

extern "C" void kernel_launch(void* const* d_in, const int* in_sizes, int n_in,
                              void* d_out, int out_size) {
    const float* instr        = (const float*)d_in[0];
    const float* distribution = (const float*)d_in[1];
    const float* sim          = (const float*)d_in[2];
    const float* rel_sim      = (const float*)d_in[3];
    const float* node_attrs   = (const float*)d_in[4];
    const float* edge_attrs   = (const float*)d_in[5];
    const float* Wnp          = (const float*)d_in[6];
    const float* We           = (const float*)d_in[7];
    const float* w_node       = (const float*)d_in[8];
    const float* w_rel        = (const float*)d_in[9];
    const int*   node_indices = (const int*)d_in[10];
    const int*   edge_batch   = (const int*)d_in[11];
    const int*   ei           = (const int*)d_in[12];
    float* out = (float*)d_out;

    cudaFuncSetAttribute(main_kernel, cudaFuncAttributeMaxDynamicSharedMemorySize, SMEM_NEED);

    zero_kernel<<<(N_NODES + 255) / 256, 256>>>();
    hist_kernel<<<NHB, 256>>>(edge_batch);
    scan_kernel<<<1, 128>>>();
    scatter_kernel<<<NHB, 256>>>(edge_batch, ei, ei + N_EDGES, distribution);
    wsplit_kernel<<<D * D / 256, 256>>>(Wnp, We, sim);
    plan_kernel<<<1, 128>>>(node_indices);
    main_kernel<<<MAX_TILES, 512, SMEM_NEED>>>(node_attrs, edge_attrs, instr, w_node, w_rel);
    softmax_kernel<<<B_GR, 256>>>(node_indices, rel_sim, out);
}

// round 6
// speedup vs baseline: 2.5077x; 1.1332x over previous
#include <cuda_runtime.h>
#include <cuda_fp16.h>
#include <cstdint>

#define D 256
#define P 8
#define B_GR 128
#define N_NODES 50000
#define N_EDGES 300000
#define NHB 148
#define MAX_TILES 3072
#define KC 32
#define NCHUNK 8
#define W_CHUNK_ELEMS (256 * KC)   // 8192 fp16 per chunk (per hi or lo)
#define WSP_HALF (129 * NCHUNK * W_CHUNK_ELEMS)

// dynamic smem byte offsets
#define OFF_INSTR 0
#define OFF_WVEC 1024
#define OFF_RED 2048               // 128 rows x 8 floats
#define OFF_A 6144                 // 2 buf x 128 rows x 40 fp16 (stride 80B), hi only
#define A_BUF_BYTES 10240
#define OFF_W 26624                // 2 buf x (hi,lo) x 256 x 40 fp16
#define W_BUF_BYTES 40960
#define W_HL_BYTES 20480
#define SMEM_NEED 108544

// ---------------- device globals ----------------
__device__ __align__(256) __half g_Wsp[2 * WSP_HALF]; // [hi/lo][widx][chunk][n=256][k=32]
__device__ float g_state_logits[N_NODES];
__device__ float g_rel_logits[N_NODES];
__device__ int g_eperm[N_EDGES];
__device__ int g_edst[N_EDGES];
__device__ float g_ecoef[N_EDGES];
__device__ int g_bintotal[B_GR];
__device__ int g_binstart[B_GR + 1];
__device__ int g_blockhist[NHB * B_GR];
__device__ int g_blockbase[NHB * B_GR];
__device__ int4 g_tiles[MAX_TILES]; // {widx, b, start, cnt}
__device__ int g_ntiles;

// ---------------- helpers ----------------
__device__ __forceinline__ uint32_t smem_u32(const void* p) {
    uint32_t a;
    asm("{ .reg .u64 t; cvta.to.shared.u64 t, %1; cvt.u32.u64 %0, t; }" : "=r"(a) : "l"(p));
    return a;
}
__device__ __forceinline__ void ldsm4(uint32_t* r, uint32_t addr) {
    asm volatile("ldmatrix.sync.aligned.m8n8.x4.shared.b16 {%0,%1,%2,%3}, [%4];"
                 : "=r"(r[0]), "=r"(r[1]), "=r"(r[2]), "=r"(r[3]) : "r"(addr));
}
__device__ __forceinline__ void mma16816(float* c, const uint32_t* a, uint32_t b0, uint32_t b1) {
    asm volatile(
        "mma.sync.aligned.m16n8k16.row.col.f32.f16.f16.f32 "
        "{%0,%1,%2,%3}, {%4,%5,%6,%7}, {%8,%9}, {%0,%1,%2,%3};"
        : "+f"(c[0]), "+f"(c[1]), "+f"(c[2]), "+f"(c[3])
        : "r"(a[0]), "r"(a[1]), "r"(a[2]), "r"(a[3]), "r"(b0), "r"(b1));
}
__device__ __forceinline__ void cpasync16(uint32_t saddr, const void* gaddr) {
    asm volatile("cp.async.cg.shared.global [%0], [%1], 16;" :: "r"(saddr), "l"(gaddr) : "memory");
}
__device__ __forceinline__ void cp_commit() { asm volatile("cp.async.commit_group;" ::: "memory"); }
__device__ __forceinline__ void cp_wait_all() { asm volatile("cp.async.wait_group 0;" ::: "memory"); }
__device__ __forceinline__ float elu1(float x) { return x > 0.f ? x : expm1f(x); }

// ---------------- prep kernels ----------------
__global__ void zero_kernel() {
    int i = blockIdx.x * blockDim.x + threadIdx.x;
    if (i < N_NODES) g_rel_logits[i] = 0.f;
    if (i < B_GR) g_bintotal[i] = 0;
    if (i < NHB * B_GR) g_blockhist[i] = 0;
}

__global__ void __launch_bounds__(256) hist_kernel(const int* __restrict__ eb) {
    __shared__ int h[B_GR];
    int t = threadIdx.x;
    if (t < B_GR) h[t] = 0;
    __syncthreads();
    for (int e = blockIdx.x * 256 + t; e < N_EDGES; e += gridDim.x * 256)
        atomicAdd(&h[eb[e]], 1);
    __syncthreads();
    if (t < B_GR) {
        g_blockhist[blockIdx.x * B_GR + t] = h[t];
        atomicAdd(&g_bintotal[t], h[t]);
    }
}

__global__ void scan_kernel() {
    __shared__ int starts[B_GR + 1];
    int b = threadIdx.x;
    if (b == 0) {
        int run = 0;
        for (int i = 0; i < B_GR; i++) { starts[i] = run; run += g_bintotal[i]; }
        starts[B_GR] = run;
        for (int i = 0; i <= B_GR; i++) g_binstart[i] = starts[i];
    }
    __syncthreads();
    if (b < B_GR) {
        int run = starts[b];
        for (int blk = 0; blk < NHB; blk++) {
            g_blockbase[blk * B_GR + b] = run;
            run += g_blockhist[blk * B_GR + b];
        }
    }
}

__global__ void __launch_bounds__(256) scatter_kernel(const int* __restrict__ eb,
                                                      const int* __restrict__ src,
                                                      const int* __restrict__ dst,
                                                      const float* __restrict__ dist) {
    __shared__ int cur[B_GR];
    int t = threadIdx.x;
    if (t < B_GR) cur[t] = g_blockbase[blockIdx.x * B_GR + t];
    __syncthreads();
    for (int e = blockIdx.x * 256 + t; e < N_EDGES; e += gridDim.x * 256) {
        int b = eb[e];
        int pos = atomicAdd(&cur[b], 1);
        g_eperm[pos] = e;
        g_edst[pos] = dst[e];
        g_ecoef[pos] = dist[src[e]];
    }
}

// split fp32 -> (hi,lo) fp16, chunk-blocked [widx][chunk][n][k32]
__device__ __forceinline__ void store_split(int widx, int n, int k, float v) {
    __half h = __float2half_rn(v);
    __half l = __float2half_rn(v - __half2float(h));
    int chunk = k >> 5, kk = k & 31;
    size_t idx = ((size_t)(widx * NCHUNK + chunk) * 256 + n) * 32 + kk;
    g_Wsp[idx] = h;
    g_Wsp[idx + WSP_HALF] = l;
}

__global__ void __launch_bounds__(256) wsplit_kernel(const float* __restrict__ Wnp,
                                                     const float* __restrict__ We,
                                                     const float* __restrict__ sim) {
    __shared__ float sim_s[B_GR * P];
    int t = threadIdx.x;
    for (int i = t; i < B_GR * P; i += 256) sim_s[i] = sim[i];
    __syncthreads();
    int pos = blockIdx.x * 256 + t;
    int n = pos >> 8, k = pos & 255;
    store_split(128, n, k, We[pos]);
    float wp[P];
#pragma unroll
    for (int p = 0; p < P; p++) wp[p] = Wnp[p * (D * D) + pos];
    for (int b = 0; b < B_GR; b++) {
        float a = 0.f;
#pragma unroll
        for (int p = 0; p < P; p++) a = fmaf(sim_s[b * P + p], wp[p], a);
        store_split(b, n, k, a);
    }
}

__device__ __forceinline__ int lower_bound_dev(const int* __restrict__ a, int n, int key) {
    int lo = 0, hi = n;
    while (lo < hi) {
        int mid = (lo + hi) >> 1;
        if (a[mid] < key) lo = mid + 1; else hi = mid;
    }
    return lo;
}

__global__ void plan_kernel(const int* __restrict__ nidx) {
    __shared__ int cnts[B_GR];
    __shared__ int starts[B_GR];
    int b = threadIdx.x;
    int elo = g_binstart[b], ecnt = g_binstart[b + 1] - elo;
    int nlo = lower_bound_dev(nidx, N_NODES, b);
    int ncnt = lower_bound_dev(nidx, N_NODES, b + 1) - nlo;
    int et = (ecnt + 127) >> 7, nt = (ncnt + 127) >> 7;
    cnts[b] = et + nt;
    __syncthreads();
    if (b == 0) {
        int run = 0;
        for (int i = 0; i < B_GR; i++) { starts[i] = run; run += cnts[i]; }
        g_ntiles = run;
    }
    __syncthreads();
    int idx = starts[b];
    for (int t = 0; t < et; t++)
        g_tiles[idx++] = make_int4(128, b, elo + t * 128, min(128, ecnt - t * 128));
    for (int t = 0; t < nt; t++)
        g_tiles[idx++] = make_int4(b, b, nlo + t * 128, min(128, ncnt - t * 128));
}

// ---------------- main HMMA kernel (2-pass fp16 split) ----------------
// 512 threads, 16 warps = 2 m-groups (64 rows) x 8 n-groups (32 cols).
__global__ void __launch_bounds__(512) main_kernel(const float* __restrict__ node_attrs,
                                                   const float* __restrict__ edge_attrs,
                                                   const float* __restrict__ instr,
                                                   const float* __restrict__ w_node,
                                                   const float* __restrict__ w_rel) {
    extern __shared__ char smem[];
    if (blockIdx.x >= g_ntiles) return;
    const int4 ti = g_tiles[blockIdx.x];
    const bool isEdge = (ti.x == 128);
    const int tid = threadIdx.x;
    const int lane = tid & 31;
    const int wid = tid >> 5;
    const int mbase = (wid & 1) * 64;
    const int ngrp = wid >> 1;
    const int nbase = ngrp * 32;

    const uint32_t sb = smem_u32(smem);
    float* instr_s = (float*)(smem + OFF_INSTR);
    float* wvec_s = (float*)(smem + OFF_WVEC);
    float* red = (float*)(smem + OFF_RED);

    if (tid < 256) {
        instr_s[tid] = instr[ti.y * D + tid];
        wvec_s[tid] = (isEdge ? w_rel : w_node)[tid];
    }

    // A row assignment: thread handles row (tid>>2), k-segment (tid&3)*8 per chunk
    const int arow = tid >> 2;
    const int kseg = (tid & 3) * 8;
    const bool valid = arow < ti.w;
    const float* rowsrc = node_attrs;
    if (valid)
        rowsrc = isEdge ? edge_attrs + (size_t)g_eperm[ti.z + arow] * D
                        : node_attrs + (size_t)(ti.z + arow) * D;

    const __half* wh = g_Wsp + (size_t)ti.x * NCHUNK * W_CHUNK_ELEMS;
    const __half* wl = wh + (size_t)WSP_HALF;

    float acc[4][4][4];
#pragma unroll
    for (int a = 0; a < 4; a++)
#pragma unroll
        for (int b = 0; b < 4; b++)
#pragma unroll
            for (int c = 0; c < 4; c++) acc[a][b][c] = 0.f;

    float4 va, vb;
#define ISSUE_W(c, buf)                                                            \
    do {                                                                           \
        uint32_t wbb = sb + OFF_W + (buf) * W_BUF_BYTES;                           \
        for (int s = tid; s < 1024; s += 512) {                                    \
            int n_ = s >> 2, ks_ = s & 3;                                          \
            uint32_t d_ = wbb + n_ * 80 + ks_ * 16;                                \
            size_t g_ = (size_t)(c) * W_CHUNK_ELEMS + n_ * 32 + ks_ * 8;           \
            cpasync16(d_, wh + g_);                                                \
            cpasync16(d_ + W_HL_BYTES, wl + g_);                                   \
        }                                                                          \
        cp_commit();                                                               \
    } while (0)

#define LDG_A(c)                                                                   \
    do {                                                                           \
        if (valid) {                                                               \
            const float4* p_ = (const float4*)(rowsrc + (c) * KC + kseg);          \
            va = __ldg(p_);                                                        \
            vb = __ldg(p_ + 1);                                                    \
        } else {                                                                   \
            va = make_float4(0.f, 0.f, 0.f, 0.f);                                  \
            vb = va;                                                               \
        }                                                                          \
    } while (0)

#define STS_A(buf)                                                                 \
    do {                                                                           \
        __half2 h0 = __floats2half2_rn(va.x, va.y);                                \
        __half2 h1 = __floats2half2_rn(va.z, va.w);                                \
        __half2 h2 = __floats2half2_rn(vb.x, vb.y);                                \
        __half2 h3 = __floats2half2_rn(vb.z, vb.w);                                \
        char* ab_ = smem + OFF_A + (buf) * A_BUF_BYTES + arow * 80 + kseg * 2;     \
        uint4 hv_;                                                                 \
        hv_.x = *(uint32_t*)&h0; hv_.y = *(uint32_t*)&h1;                          \
        hv_.z = *(uint32_t*)&h2; hv_.w = *(uint32_t*)&h3;                          \
        *(uint4*)ab_ = hv_;                                                        \
    } while (0)

    // prologue
    ISSUE_W(0, 0);
    LDG_A(0);
    STS_A(0);

#pragma unroll 1
    for (int c = 0; c < NCHUNK; c++) {
        cp_wait_all();
        __syncthreads();
        const int buf = c & 1;
        if (c + 1 < NCHUNK) {
            ISSUE_W(c + 1, buf ^ 1);
            LDG_A(c + 1);
        }
        const uint32_t abase = sb + OFF_A + buf * A_BUF_BYTES;
        const uint32_t wbase = sb + OFF_W + buf * W_BUF_BYTES;
#pragma unroll
        for (int ks = 0; ks < 2; ks++) {
            const int k0 = ks * 16;
            uint32_t ah[4][4];
#pragma unroll
            for (int mi = 0; mi < 4; mi++) {
                uint32_t ra = abase + (mbase + mi * 16 + (lane & 15)) * 80 + k0 * 2 + ((lane >> 4) * 16);
                ldsm4(ah[mi], ra);
            }
#pragma unroll
            for (int nip = 0; nip < 2; nip++) {
                const int n0 = nbase + nip * 16;
                uint32_t rb = wbase + (n0 + ((lane >> 4) << 3) + (lane & 7)) * 80 + k0 * 2 +
                              (((lane >> 3) & 1) * 16);
                uint32_t bh[4], bl[4];
                ldsm4(bh, rb);
                ldsm4(bl, rb + W_HL_BYTES);
#pragma unroll
                for (int mi = 0; mi < 4; mi++) {
                    mma16816(acc[mi][nip * 2 + 0], ah[mi], bh[0], bh[1]);
                    mma16816(acc[mi][nip * 2 + 1], ah[mi], bh[2], bh[3]);
                    mma16816(acc[mi][nip * 2 + 0], ah[mi], bl[0], bl[1]);
                    mma16816(acc[mi][nip * 2 + 1], ah[mi], bl[2], bl[3]);
                }
            }
        }
        if (c + 1 < NCHUNK) STS_A(buf ^ 1);
    }

    // ---- epilogue: per-row v = sum_d w[d]*elu(instr[d]*x[d]) ----
#pragma unroll
    for (int mi = 0; mi < 4; mi++) {
        float pr0 = 0.f, pr1 = 0.f;
#pragma unroll
        for (int ni = 0; ni < 4; ni++) {
            int c0 = nbase + ni * 8 + (lane & 3) * 2;
            float w0 = wvec_s[c0], w1 = wvec_s[c0 + 1];
            float i0 = instr_s[c0], i1 = instr_s[c0 + 1];
            pr0 += w0 * elu1(i0 * acc[mi][ni][0]) + w1 * elu1(i1 * acc[mi][ni][1]);
            pr1 += w0 * elu1(i0 * acc[mi][ni][2]) + w1 * elu1(i1 * acc[mi][ni][3]);
        }
        pr0 += __shfl_xor_sync(0xFFFFFFFFu, pr0, 1);
        pr0 += __shfl_xor_sync(0xFFFFFFFFu, pr0, 2);
        pr1 += __shfl_xor_sync(0xFFFFFFFFu, pr1, 1);
        pr1 += __shfl_xor_sync(0xFFFFFFFFu, pr1, 2);
        if ((lane & 3) == 0) {
            int row = mbase + mi * 16 + (lane >> 2);
            red[row * 8 + ngrp] = pr0;
            red[(row + 8) * 8 + ngrp] = pr1;
        }
    }
    __syncthreads();
    if (tid < 128 && tid < ti.w) {
        float v = 0.f;
#pragma unroll
        for (int g = 0; g < 8; g++) v += red[tid * 8 + g];
        int gl = ti.z + tid;
        if (isEdge) atomicAdd(&g_rel_logits[g_edst[gl]], g_ecoef[gl] * v);
        else g_state_logits[gl] = v;
    }
#undef ISSUE_W
#undef LDG_A
#undef STS_A
}

// ---------------- segment softmax + combine ----------------
__global__ void __launch_bounds__(256) softmax_kernel(const int* __restrict__ nidx,
                                                      const float* __restrict__ rel_sim,
                                                      float* __restrict__ out) {
    const int b = blockIdx.x;
    const int t = threadIdx.x;
    __shared__ float sh[256];
    __shared__ int bounds[2];
    if (t == 0) {
        bounds[0] = lower_bound_dev(nidx, N_NODES, b);
        bounds[1] = lower_bound_dev(nidx, N_NODES, b + 1);
    }
    __syncthreads();
    const int lo = bounds[0], hi = bounds[1];
    if (hi <= lo) return;

    float m1 = -1e30f, m2 = -1e30f;
    for (int i = lo + t; i < hi; i += 256) {
        m1 = fmaxf(m1, g_state_logits[i]);
        m2 = fmaxf(m2, g_rel_logits[i]);
    }
    sh[t] = m1; __syncthreads();
    for (int o = 128; o > 0; o >>= 1) { if (t < o) sh[t] = fmaxf(sh[t], sh[t + o]); __syncthreads(); }
    m1 = sh[0]; __syncthreads();
    sh[t] = m2; __syncthreads();
    for (int o = 128; o > 0; o >>= 1) { if (t < o) sh[t] = fmaxf(sh[t], sh[t + o]); __syncthreads(); }
    m2 = sh[0]; __syncthreads();

    float s1 = 0.f, s2 = 0.f;
    for (int i = lo + t; i < hi; i += 256) {
        s1 += expf(g_state_logits[i] - m1);
        s2 += expf(g_rel_logits[i] - m2);
    }
    sh[t] = s1; __syncthreads();
    for (int o = 128; o > 0; o >>= 1) { if (t < o) sh[t] += sh[t + o]; __syncthreads(); }
    s1 = sh[0]; __syncthreads();
    sh[t] = s2; __syncthreads();
    for (int o = 128; o > 0; o >>= 1) { if (t < o) sh[t] += sh[t + o]; __syncthreads(); }
    s2 = sh[0]; __syncthreads();

    const float r = rel_sim[b];
    const float inv1 = 1.f / s1, inv2 = 1.f / s2;
    for (int i = lo + t; i < hi; i += 256) {
        float ns = expf(g_state_logits[i] - m1) * inv1;
        float nr = expf(g_rel_logits[i] - m2) * inv2;
        out[i] = r * nr + (1.f - r) * ns;
    }
}

extern "C" void kernel_launch(void* const* d_in, const int* in_sizes, int n_in,
                              void* d_out, int out_size) {
    const float* instr        = (const float*)d_in[0];
    const float* distribution = (const float*)d_in[1];
    const float* sim          = (const float*)d_in[2];
    const float* rel_sim      = (const float*)d_in[3];
    const float* node_attrs   = (const float*)d_in[4];
    const float* edge_attrs   = (const float*)d_in[5];
    const float* Wnp          = (const float*)d_in[6];
    const float* We           = (const float*)d_in[7];
    const float* w_node       = (const float*)d_in[8];
    const float* w_rel        = (const float*)d_in[9];
    const int*   node_indices = (const int*)d_in[10];
    const int*   edge_batch   = (const int*)d_in[11];
    const int*   ei           = (const int*)d_in[12];
    float* out = (float*)d_out;

    cudaFuncSetAttribute(main_kernel, cudaFuncAttributeMaxDynamicSharedMemorySize, SMEM_NEED);

    zero_kernel<<<(N_NODES + 255) / 256, 256>>>();
    hist_kernel<<<NHB, 256>>>(edge_batch);
    scan_kernel<<<1, 128>>>();
    scatter_kernel<<<NHB, 256>>>(edge_batch, ei, ei + N_EDGES, distribution);
    wsplit_kernel<<<D * D / 256, 256>>>(Wnp, We, sim);
    plan_kernel<<<1, 128>>>(node_indices);
    main_kernel<<<MAX_TILES, 512, SMEM_NEED>>>(node_attrs, edge_attrs, instr, w_node, w_rel);
    softmax_kernel<<<B_GR, 256>>>(node_indices, rel_sim, out);
}

// round 9
// speedup vs baseline: 2.5962x; 1.0353x over previous
#include <cuda_runtime.h>
#include <cuda_fp16.h>
#include <cstdint>

#define D 256
#define P 8
#define B_GR 128
#define N_NODES 50000
#define N_EDGES 300000
#define NHB 148
#define MAX_TILES 3072
#define KC 32
#define NCHUNK 8
#define W_CHUNK_ELEMS (256 * KC)   // 8192 fp16 per chunk (per hi or lo)
#define WSP_HALF (129 * NCHUNK * W_CHUNK_ELEMS)

// dynamic smem byte offsets (per CTA, half-tile: N=128)
#define OFF_INSTR 0
#define OFF_WVEC 1024
#define OFF_RED 2048                // 128 rows x 4 floats
#define OFF_A 4096                  // 2 buf x (hi,lo) x 128 rows x 40 fp16 (80B stride)
#define A_BUF_BYTES 20480           // hi+lo for one buffer
#define A_HL_BYTES 10240
#define OFF_W 45056                 // 3 buf x (hi,lo) x 128 n x 40 fp16
#define W_BUF_BYTES 20480
#define W_HL_BYTES 10240
#define SMEM_NEED 106496

// ---------------- device globals ----------------
__device__ __align__(256) __half g_Wsp[2 * WSP_HALF]; // [hi/lo][widx][chunk][n=256][k=32]
__device__ float g_state_logits[N_NODES];
__device__ float g_rel_logits[N_NODES];
__device__ int g_eperm[N_EDGES];
__device__ int g_edst[N_EDGES];
__device__ float g_ecoef[N_EDGES];
__device__ int g_bintotal[B_GR];
__device__ int g_binstart[B_GR + 1];
__device__ int g_blockhist[NHB * B_GR];
__device__ int g_blockbase[NHB * B_GR];
__device__ int4 g_tiles[MAX_TILES]; // {widx, b, start, cnt}
__device__ int g_ntiles;

// ---------------- helpers ----------------
__device__ __forceinline__ uint32_t smem_u32(const void* p) {
    uint32_t a;
    asm("{ .reg .u64 t; cvta.to.shared.u64 t, %1; cvt.u32.u64 %0, t; }" : "=r"(a) : "l"(p));
    return a;
}
__device__ __forceinline__ void ldsm4(uint32_t* r, uint32_t addr) {
    asm volatile("ldmatrix.sync.aligned.m8n8.x4.shared.b16 {%0,%1,%2,%3}, [%4];"
                 : "=r"(r[0]), "=r"(r[1]), "=r"(r[2]), "=r"(r[3]) : "r"(addr));
}
__device__ __forceinline__ void mma16816(float* c, const uint32_t* a, uint32_t b0, uint32_t b1) {
    asm volatile(
        "mma.sync.aligned.m16n8k16.row.col.f32.f16.f16.f32 "
        "{%0,%1,%2,%3}, {%4,%5,%6,%7}, {%8,%9}, {%0,%1,%2,%3};"
        : "+f"(c[0]), "+f"(c[1]), "+f"(c[2]), "+f"(c[3])
        : "r"(a[0]), "r"(a[1]), "r"(a[2]), "r"(a[3]), "r"(b0), "r"(b1));
}
__device__ __forceinline__ void cpasync16(uint32_t saddr, const void* gaddr) {
    asm volatile("cp.async.cg.shared.global [%0], [%1], 16;" :: "r"(saddr), "l"(gaddr) : "memory");
}
__device__ __forceinline__ void cp_commit() { asm volatile("cp.async.commit_group;" ::: "memory"); }
__device__ __forceinline__ void cp_wait_all() { asm volatile("cp.async.wait_group 0;" ::: "memory"); }
__device__ __forceinline__ void cp_wait_1() { asm volatile("cp.async.wait_group 1;" ::: "memory"); }
__device__ __forceinline__ float elu1(float x) { return x > 0.f ? x : expm1f(x); }

// ---------------- prep kernels ----------------
__global__ void zero_kernel() {
    int i = blockIdx.x * blockDim.x + threadIdx.x;
    if (i < N_NODES) { g_rel_logits[i] = 0.f; g_state_logits[i] = 0.f; }
    if (i < B_GR) g_bintotal[i] = 0;
    if (i < NHB * B_GR) g_blockhist[i] = 0;
}

__global__ void __launch_bounds__(256) hist_kernel(const int* __restrict__ eb) {
    __shared__ int h[B_GR];
    int t = threadIdx.x;
    if (t < B_GR) h[t] = 0;
    __syncthreads();
    for (int e = blockIdx.x * 256 + t; e < N_EDGES; e += gridDim.x * 256)
        atomicAdd(&h[eb[e]], 1);
    __syncthreads();
    if (t < B_GR) {
        g_blockhist[blockIdx.x * B_GR + t] = h[t];
        atomicAdd(&g_bintotal[t], h[t]);
    }
}

__global__ void scan_kernel() {
    __shared__ int starts[B_GR + 1];
    int b = threadIdx.x;
    if (b == 0) {
        int run = 0;
        for (int i = 0; i < B_GR; i++) { starts[i] = run; run += g_bintotal[i]; }
        starts[B_GR] = run;
        for (int i = 0; i <= B_GR; i++) g_binstart[i] = starts[i];
    }
    __syncthreads();
    if (b < B_GR) {
        int run = starts[b];
        for (int blk = 0; blk < NHB; blk++) {
            g_blockbase[blk * B_GR + b] = run;
            run += g_blockhist[blk * B_GR + b];
        }
    }
}

__global__ void __launch_bounds__(256) scatter_kernel(const int* __restrict__ eb,
                                                      const int* __restrict__ src,
                                                      const int* __restrict__ dst,
                                                      const float* __restrict__ dist) {
    __shared__ int cur[B_GR];
    int t = threadIdx.x;
    if (t < B_GR) cur[t] = g_blockbase[blockIdx.x * B_GR + t];
    __syncthreads();
    for (int e = blockIdx.x * 256 + t; e < N_EDGES; e += gridDim.x * 256) {
        int b = eb[e];
        int pos = atomicAdd(&cur[b], 1);
        g_eperm[pos] = e;
        g_edst[pos] = dst[e];
        g_ecoef[pos] = dist[src[e]];
    }
}

// split fp32 -> (hi,lo) fp16, chunk-blocked [widx][chunk][n][k32]
__device__ __forceinline__ void store_split(int widx, int n, int k, float v) {
    __half h = __float2half_rn(v);
    __half l = __float2half_rn(v - __half2float(h));
    int chunk = k >> 5, kk = k & 31;
    size_t idx = ((size_t)(widx * NCHUNK + chunk) * 256 + n) * 32 + kk;
    g_Wsp[idx] = h;
    g_Wsp[idx + WSP_HALF] = l;
}

__global__ void __launch_bounds__(256) wsplit_kernel(const float* __restrict__ Wnp,
                                                     const float* __restrict__ We,
                                                     const float* __restrict__ sim) {
    __shared__ float sim_s[B_GR * P];
    int t = threadIdx.x;
    for (int i = t; i < B_GR * P; i += 256) sim_s[i] = sim[i];
    __syncthreads();
    int pos = blockIdx.x * 256 + t;
    int n = pos >> 8, k = pos & 255;
    store_split(128, n, k, We[pos]);
    float wp[P];
#pragma unroll
    for (int p = 0; p < P; p++) wp[p] = Wnp[p * (D * D) + pos];
    for (int b = 0; b < B_GR; b++) {
        float a = 0.f;
#pragma unroll
        for (int p = 0; p < P; p++) a = fmaf(sim_s[b * P + p], wp[p], a);
        store_split(b, n, k, a);
    }
}

__device__ __forceinline__ int lower_bound_dev(const int* __restrict__ a, int n, int key) {
    int lo = 0, hi = n;
    while (lo < hi) {
        int mid = (lo + hi) >> 1;
        if (a[mid] < key) lo = mid + 1; else hi = mid;
    }
    return lo;
}

__global__ void plan_kernel(const int* __restrict__ nidx) {
    __shared__ int cnts[B_GR];
    __shared__ int starts[B_GR];
    int b = threadIdx.x;
    int elo = g_binstart[b], ecnt = g_binstart[b + 1] - elo;
    int nlo = lower_bound_dev(nidx, N_NODES, b);
    int ncnt = lower_bound_dev(nidx, N_NODES, b + 1) - nlo;
    int et = (ecnt + 127) >> 7, nt = (ncnt + 127) >> 7;
    cnts[b] = et + nt;
    __syncthreads();
    if (b == 0) {
        int run = 0;
        for (int i = 0; i < B_GR; i++) { starts[i] = run; run += cnts[i]; }
        g_ntiles = run;
    }
    __syncthreads();
    int idx = starts[b];
    for (int t = 0; t < et; t++)
        g_tiles[idx++] = make_int4(128, b, elo + t * 128, min(128, ecnt - t * 128));
    for (int t = 0; t < nt; t++)
        g_tiles[idx++] = make_int4(b, b, nlo + t * 128, min(128, ncnt - t * 128));
}

// ---------------- main HMMA kernel (3-pass fp16 split, N-split, 3 W buffers) ----------------
// 256 threads, 8 warps = 2 m-groups (64 rows) x 4 n-groups (32 cols of this half).
__global__ void __launch_bounds__(256, 2) main_kernel(const float* __restrict__ node_attrs,
                                                      const float* __restrict__ edge_attrs,
                                                      const float* __restrict__ instr,
                                                      const float* __restrict__ w_node,
                                                      const float* __restrict__ w_rel) {
    extern __shared__ char smem[];
    const int tb = blockIdx.x >> 1;
    if (tb >= g_ntiles) return;
    const int half = blockIdx.x & 1;
    const int nofs = half * 128;
    const int4 ti = g_tiles[tb];
    const bool isEdge = (ti.x == 128);
    const int tid = threadIdx.x;
    const int lane = tid & 31;
    const int wid = tid >> 5;
    const int mbase = (wid & 1) * 64;
    const int ngrp = wid >> 1;           // 0..3

    const uint32_t sb = smem_u32(smem);
    float* instr_s = (float*)(smem + OFF_INSTR);
    float* wvec_s = (float*)(smem + OFF_WVEC);
    float* red = (float*)(smem + OFF_RED);

    instr_s[tid] = instr[ti.y * D + tid];
    wvec_s[tid] = (isEdge ? w_rel : w_node)[tid];

    // A staging: 2 threads per row; thread covers 16 k-floats per chunk
    const int arow = tid >> 1;
    const int kseg = (tid & 1) * 16;
    const bool valid = arow < ti.w;
    const float* rowsrc = node_attrs;
    if (valid)
        rowsrc = isEdge ? edge_attrs + (size_t)g_eperm[ti.z + arow] * D
                        : node_attrs + (size_t)(ti.z + arow) * D;

    const __half* wh = g_Wsp + (size_t)ti.x * NCHUNK * W_CHUNK_ELEMS + (size_t)nofs * 32;

    float acc[4][4][4];
#pragma unroll
    for (int a = 0; a < 4; a++)
#pragma unroll
        for (int b = 0; b < 4; b++)
#pragma unroll
            for (int c = 0; c < 4; c++) acc[a][b][c] = 0.f;

    float4 va, vb, vc, vd;
#define ISSUE_W(c, buf)                                                             \
    do {                                                                            \
        uint32_t wbb = sb + OFF_W + (buf) * W_BUF_BYTES;                            \
        const __half* whc = wh + (size_t)(c) * W_CHUNK_ELEMS;                       \
        for (int s = tid; s < 512; s += 256) {                                      \
            int n_ = s >> 2, ks_ = s & 3;                                           \
            uint32_t d_ = wbb + n_ * 80 + ks_ * 16;                                 \
            size_t g_ = (size_t)n_ * 32 + ks_ * 8;                                  \
            cpasync16(d_, whc + g_);                                                \
            cpasync16(d_ + W_HL_BYTES, whc + WSP_HALF + g_);                        \
        }                                                                           \
        cp_commit();                                                                \
    } while (0)

#define LDG_A(c)                                                                    \
    do {                                                                            \
        if (valid) {                                                                \
            const float4* p_ = (const float4*)(rowsrc + (c) * KC + kseg);           \
            va = __ldg(p_); vb = __ldg(p_ + 1);                                     \
            vc = __ldg(p_ + 2); vd = __ldg(p_ + 3);                                 \
        } else {                                                                    \
            va = make_float4(0.f, 0.f, 0.f, 0.f);                                   \
            vb = va; vc = va; vd = va;                                              \
        }                                                                           \
    } while (0)

#define CVT1(h2, l2, x, y)                                                          \
    do {                                                                            \
        h2 = __floats2half2_rn(x, y);                                               \
        l2 = __floats2half2_rn((x) - __half2float(__low2half(h2)),                  \
                               (y) - __half2float(__high2half(h2)));                \
    } while (0)

#define STS_A(buf)                                                                  \
    do {                                                                            \
        __half2 h0, h1, h2, h3, h4, h5, h6, h7;                                     \
        __half2 l0, l1, l2, l3, l4, l5, l6, l7;                                     \
        CVT1(h0, l0, va.x, va.y); CVT1(h1, l1, va.z, va.w);                         \
        CVT1(h2, l2, vb.x, vb.y); CVT1(h3, l3, vb.z, vb.w);                         \
        CVT1(h4, l4, vc.x, vc.y); CVT1(h5, l5, vc.z, vc.w);                         \
        CVT1(h6, l6, vd.x, vd.y); CVT1(h7, l7, vd.z, vd.w);                         \
        char* ab_ = smem + OFF_A + (buf) * A_BUF_BYTES + arow * 80 + kseg * 2;      \
        uint4 u0, u1, v0, v1;                                                       \
        u0.x = *(uint32_t*)&h0; u0.y = *(uint32_t*)&h1;                             \
        u0.z = *(uint32_t*)&h2; u0.w = *(uint32_t*)&h3;                             \
        u1.x = *(uint32_t*)&h4; u1.y = *(uint32_t*)&h5;                             \
        u1.z = *(uint32_t*)&h6; u1.w = *(uint32_t*)&h7;                             \
        v0.x = *(uint32_t*)&l0; v0.y = *(uint32_t*)&l1;                             \
        v0.z = *(uint32_t*)&l2; v0.w = *(uint32_t*)&l3;                             \
        v1.x = *(uint32_t*)&l4; v1.y = *(uint32_t*)&l5;                             \
        v1.z = *(uint32_t*)&l6; v1.w = *(uint32_t*)&l7;                             \
        *(uint4*)ab_ = u0;                                                          \
        *(uint4*)(ab_ + 16) = u1;                                                   \
        *(uint4*)(ab_ + A_HL_BYTES) = v0;                                           \
        *(uint4*)(ab_ + A_HL_BYTES + 16) = v1;                                      \
    } while (0)

    // prologue: issue chunk 0 and 1 (buffers 0, 1), stage A chunk 0
    ISSUE_W(0, 0);
    LDG_A(0);
    STS_A(0);
    ISSUE_W(1, 1);

#pragma unroll 1
    for (int c = 0; c < NCHUNK; c++) {
        if (c == NCHUNK - 1) cp_wait_all(); else cp_wait_1();
        __syncthreads();
        // Safe 2-deep prefetch: buffer (c+2)%3 was last read in iteration c-1;
        // the barrier above proves all warps are past it.
        if (c + 2 < NCHUNK) ISSUE_W(c + 2, (c + 2) % 3);
        if (c + 1 < NCHUNK) LDG_A(c + 1);
        const int abuf = c & 1;
        const uint32_t abase = sb + OFF_A + abuf * A_BUF_BYTES;
        const uint32_t wbase = sb + OFF_W + (c % 3) * W_BUF_BYTES;
#pragma unroll
        for (int ks = 0; ks < 2; ks++) {
            const int k0 = ks * 16;
            uint32_t ah[4][4], al[4][4];
#pragma unroll
            for (int mi = 0; mi < 4; mi++) {
                uint32_t ra = abase + (mbase + mi * 16 + (lane & 15)) * 80 + k0 * 2 + ((lane >> 4) * 16);
                ldsm4(ah[mi], ra);
                ldsm4(al[mi], ra + A_HL_BYTES);
            }
#pragma unroll
            for (int nip = 0; nip < 2; nip++) {
                const int nloc = ngrp * 32 + nip * 16;
                uint32_t rb = wbase + (nloc + ((lane >> 4) << 3) + (lane & 7)) * 80 + k0 * 2 +
                              (((lane >> 3) & 1) * 16);
                uint32_t bh[4], bl[4];
                ldsm4(bh, rb);
                ldsm4(bl, rb + W_HL_BYTES);
#pragma unroll
                for (int mi = 0; mi < 4; mi++) {
                    mma16816(acc[mi][nip * 2 + 0], ah[mi], bh[0], bh[1]);
                    mma16816(acc[mi][nip * 2 + 1], ah[mi], bh[2], bh[3]);
                    mma16816(acc[mi][nip * 2 + 0], ah[mi], bl[0], bl[1]);
                    mma16816(acc[mi][nip * 2 + 1], ah[mi], bl[2], bl[3]);
                    mma16816(acc[mi][nip * 2 + 0], al[mi], bh[0], bh[1]);
                    mma16816(acc[mi][nip * 2 + 1], al[mi], bh[2], bh[3]);
                }
            }
        }
        if (c + 1 < NCHUNK) STS_A(abuf ^ 1);
    }

    // ---- epilogue: per-row partial over this half's 128 columns ----
#pragma unroll
    for (int mi = 0; mi < 4; mi++) {
        float pr0 = 0.f, pr1 = 0.f;
#pragma unroll
        for (int ni = 0; ni < 4; ni++) {
            int c0 = nofs + ngrp * 32 + ni * 8 + (lane & 3) * 2;
            float w0 = wvec_s[c0], w1 = wvec_s[c0 + 1];
            float i0 = instr_s[c0], i1 = instr_s[c0 + 1];
            pr0 += w0 * elu1(i0 * acc[mi][ni][0]) + w1 * elu1(i1 * acc[mi][ni][1]);
            pr1 += w0 * elu1(i0 * acc[mi][ni][2]) + w1 * elu1(i1 * acc[mi][ni][3]);
        }
        pr0 += __shfl_xor_sync(0xFFFFFFFFu, pr0, 1);
        pr0 += __shfl_xor_sync(0xFFFFFFFFu, pr0, 2);
        pr1 += __shfl_xor_sync(0xFFFFFFFFu, pr1, 1);
        pr1 += __shfl_xor_sync(0xFFFFFFFFu, pr1, 2);
        if ((lane & 3) == 0) {
            int row = mbase + mi * 16 + (lane >> 2);
            red[row * 4 + ngrp] = pr0;
            red[(row + 8) * 4 + ngrp] = pr1;
        }
    }
    __syncthreads();
    if (tid < 128 && tid < ti.w) {
        float v = red[tid * 4] + red[tid * 4 + 1] + red[tid * 4 + 2] + red[tid * 4 + 3];
        int gl = ti.z + tid;
        if (isEdge) atomicAdd(&g_rel_logits[g_edst[gl]], g_ecoef[gl] * v);
        else atomicAdd(&g_state_logits[gl], v);
    }
#undef ISSUE_W
#undef LDG_A
#undef CVT1
#undef STS_A
}

// ---------------- segment softmax + combine ----------------
__global__ void __launch_bounds__(256) softmax_kernel(const int* __restrict__ nidx,
                                                      const float* __restrict__ rel_sim,
                                                      float* __restrict__ out) {
    const int b = blockIdx.x;
    const int t = threadIdx.x;
    __shared__ float sh[256];
    __shared__ int bounds[2];
    if (t == 0) {
        bounds[0] = lower_bound_dev(nidx, N_NODES, b);
        bounds[1] = lower_bound_dev(nidx, N_NODES, b + 1);
    }
    __syncthreads();
    const int lo = bounds[0], hi = bounds[1];
    if (hi <= lo) return;

    float m1 = -1e30f, m2 = -1e30f;
    for (int i = lo + t; i < hi; i += 256) {
        m1 = fmaxf(m1, g_state_logits[i]);
        m2 = fmaxf(m2, g_rel_logits[i]);
    }
    sh[t] = m1; __syncthreads();
    for (int o = 128; o > 0; o >>= 1) { if (t < o) sh[t] = fmaxf(sh[t], sh[t + o]); __syncthreads(); }
    m1 = sh[0]; __syncthreads();
    sh[t] = m2; __syncthreads();
    for (int o = 128; o > 0; o >>= 1) { if (t < o) sh[t] = fmaxf(sh[t], sh[t + o]); __syncthreads(); }
    m2 = sh[0]; __syncthreads();

    float s1 = 0.f, s2 = 0.f;
    for (int i = lo + t; i < hi; i += 256) {
        s1 += expf(g_state_logits[i] - m1);
        s2 += expf(g_rel_logits[i] - m2);
    }
    sh[t] = s1; __syncthreads();
    for (int o = 128; o > 0; o >>= 1) { if (t < o) sh[t] += sh[t + o]; __syncthreads(); }
    s1 = sh[0]; __syncthreads();
    sh[t] = s2; __syncthreads();
    for (int o = 128; o > 0; o >>= 1) { if (t < o) sh[t] += sh[t + o]; __syncthreads(); }
    s2 = sh[0]; __syncthreads();

    const float r = rel_sim[b];
    const float inv1 = 1.f / s1, inv2 = 1.f / s2;
    for (int i = lo + t; i < hi; i += 256) {
        float ns = expf(g_state_logits[i] - m1) * inv1;
        float nr = expf(g_rel_logits[i] - m2) * inv2;
        out[i] = r * nr + (1.f - r) * ns;
    }
}

extern "C" void kernel_launch(void* const* d_in, const int* in_sizes, int n_in,
                              void* d_out, int out_size) {
    const float* instr        = (const float*)d_in[0];
    const float* distribution = (const float*)d_in[1];
    const float* sim          = (const float*)d_in[2];
    const float* rel_sim      = (const float*)d_in[3];
    const float* node_attrs   = (const float*)d_in[4];
    const float* edge_attrs   = (const float*)d_in[5];
    const float* Wnp          = (const float*)d_in[6];
    const float* We           = (const float*)d_in[7];
    const float* w_node       = (const float*)d_in[8];
    const float* w_rel        = (const float*)d_in[9];
    const int*   node_indices = (const int*)d_in[10];
    const int*   edge_batch   = (const int*)d_in[11];
    const int*   ei           = (const int*)d_in[12];
    float* out = (float*)d_out;

    cudaFuncSetAttribute(main_kernel, cudaFuncAttributeMaxDynamicSharedMemorySize, SMEM_NEED);

    zero_kernel<<<(N_NODES + 255) / 256, 256>>>();
    hist_kernel<<<NHB, 256>>>(edge_batch);
    scan_kernel<<<1, 128>>>();
    scatter_kernel<<<NHB, 256>>>(edge_batch, ei, ei + N_EDGES, distribution);
    wsplit_kernel<<<D * D / 256, 256>>>(Wnp, We, sim);
    plan_kernel<<<1, 128>>>(node_indices);
    main_kernel<<<2 * MAX_TILES, 256, SMEM_NEED>>>(node_attrs, edge_attrs, instr, w_node, w_rel);
    softmax_kernel<<<B_GR, 256>>>(node_indices, rel_sim, out);
}

// round 10
// speedup vs baseline: 2.7493x; 1.0590x over previous
#include <cuda_runtime.h>
#include <cuda_fp16.h>
#include <cstdint>

#define D 256
#define P 8
#define B_GR 128
#define N_NODES 50000
#define N_EDGES 300000
#define NHB 148
#define MAX_TILES 3072
#define KC 32
#define NCHUNK 8
#define W_CHUNK_ELEMS (256 * KC)   // 8192 fp16 per chunk (per hi or lo)
#define WSP_HALF (129 * NCHUNK * W_CHUNK_ELEMS)

// dynamic smem byte offsets (per CTA, half-tile: N=128)
#define OFF_INSTR 0
#define OFF_WVEC 1024
#define OFF_RED 2048                // 128 rows x 4 floats
#define OFF_A 4096                  // 2 buf x (hi,lo) x 128 rows x 40 fp16 (80B stride)
#define A_BUF_BYTES 20480           // hi+lo for one buffer
#define A_HL_BYTES 10240
#define OFF_W 45056                 // 3 buf x (hi,lo) x 128 n x 40 fp16
#define W_BUF_BYTES 20480
#define W_HL_BYTES 10240
#define SMEM_NEED 106496

#define ZBLK ((N_NODES + 255) / 256)   // 196
#define WSBLK (D * D / 256)            // 256

// ---------------- device globals ----------------
__device__ __align__(256) __half g_Wsp[2 * WSP_HALF]; // [hi/lo][widx][chunk][n=256][k=32]
__device__ float g_state_logits[N_NODES];
__device__ float g_rel_logits[N_NODES];
__device__ int g_eperm[N_EDGES];
__device__ int g_edst[N_EDGES];
__device__ float g_ecoef[N_EDGES];
__device__ int g_binstart[B_GR + 1];
__device__ int g_blockhist[NHB * B_GR];
__device__ int g_blockbase[NHB * B_GR];
__device__ int4 g_tiles[MAX_TILES]; // {widx, b, start, cnt}
__device__ int g_ntiles;

// ---------------- helpers ----------------
__device__ __forceinline__ uint32_t smem_u32(const void* p) {
    uint32_t a;
    asm("{ .reg .u64 t; cvta.to.shared.u64 t, %1; cvt.u32.u64 %0, t; }" : "=r"(a) : "l"(p));
    return a;
}
__device__ __forceinline__ void ldsm4(uint32_t* r, uint32_t addr) {
    asm volatile("ldmatrix.sync.aligned.m8n8.x4.shared.b16 {%0,%1,%2,%3}, [%4];"
                 : "=r"(r[0]), "=r"(r[1]), "=r"(r[2]), "=r"(r[3]) : "r"(addr));
}
__device__ __forceinline__ void mma16816(float* c, const uint32_t* a, uint32_t b0, uint32_t b1) {
    asm volatile(
        "mma.sync.aligned.m16n8k16.row.col.f32.f16.f16.f32 "
        "{%0,%1,%2,%3}, {%4,%5,%6,%7}, {%8,%9}, {%0,%1,%2,%3};"
        : "+f"(c[0]), "+f"(c[1]), "+f"(c[2]), "+f"(c[3])
        : "r"(a[0]), "r"(a[1]), "r"(a[2]), "r"(a[3]), "r"(b0), "r"(b1));
}
__device__ __forceinline__ void cpasync16(uint32_t saddr, const void* gaddr) {
    asm volatile("cp.async.cg.shared.global [%0], [%1], 16;" :: "r"(saddr), "l"(gaddr) : "memory");
}
__device__ __forceinline__ void cp_commit() { asm volatile("cp.async.commit_group;" ::: "memory"); }
__device__ __forceinline__ void cp_wait_all() { asm volatile("cp.async.wait_group 0;" ::: "memory"); }
__device__ __forceinline__ void cp_wait_1() { asm volatile("cp.async.wait_group 1;" ::: "memory"); }
__device__ __forceinline__ float elu1(float x) { return x > 0.f ? x : expm1f(x); }

// ---------------- L0: hist (blocks 0..NHB-1) + zero logits (rest) ----------------
__global__ void __launch_bounds__(256) l0_kernel(const int* __restrict__ eb) {
    int blk = blockIdx.x;
    int t = threadIdx.x;
    if (blk < NHB) {
        __shared__ int h[B_GR];
        if (t < B_GR) h[t] = 0;
        __syncthreads();
        for (int e = blk * 256 + t; e < N_EDGES; e += NHB * 256)
            atomicAdd(&h[eb[e]], 1);
        __syncthreads();
        if (t < B_GR) g_blockhist[blk * B_GR + t] = h[t];
    } else {
        int i = (blk - NHB) * 256 + t;
        if (i < N_NODES) { g_rel_logits[i] = 0.f; g_state_logits[i] = 0.f; }
    }
}

// ---------------- L1: scan ----------------
__global__ void scan_kernel() {
    __shared__ int tot[B_GR];
    __shared__ int starts[B_GR + 1];
    int b = threadIdx.x;  // 128 threads
    int s = 0;
    for (int blk = 0; blk < NHB; blk++) s += g_blockhist[blk * B_GR + b];
    tot[b] = s;
    __syncthreads();
    if (b == 0) {
        int run = 0;
        for (int i = 0; i < B_GR; i++) { starts[i] = run; run += tot[i]; }
        starts[B_GR] = run;
        for (int i = 0; i <= B_GR; i++) g_binstart[i] = starts[i];
    }
    __syncthreads();
    {
        int run = starts[b];
        for (int blk = 0; blk < NHB; blk++) {
            g_blockbase[blk * B_GR + b] = run;
            run += g_blockhist[blk * B_GR + b];
        }
    }
}

// fp32 -> (hi,lo) fp16, chunk-blocked [widx][chunk][n][k32]
__device__ __forceinline__ void store_split(int widx, int n, int k, float v) {
    __half h = __float2half_rn(v);
    __half l = __float2half_rn(v - __half2float(h));
    int chunk = k >> 5, kk = k & 31;
    size_t idx = ((size_t)(widx * NCHUNK + chunk) * 256 + n) * 32 + kk;
    g_Wsp[idx] = h;
    g_Wsp[idx + WSP_HALF] = l;
}

__device__ __forceinline__ int lower_bound_dev(const int* __restrict__ a, int n, int key) {
    int lo = 0, hi = n;
    while (lo < hi) {
        int mid = (lo + hi) >> 1;
        if (a[mid] < key) lo = mid + 1; else hi = mid;
    }
    return lo;
}

// ---------------- L2: scatter (0..147) + wsplit (148..403) + plan (404) ----------------
__global__ void __launch_bounds__(256) l2_kernel(const int* __restrict__ eb,
                                                 const int* __restrict__ src,
                                                 const int* __restrict__ dst,
                                                 const float* __restrict__ dist,
                                                 const float* __restrict__ Wnp,
                                                 const float* __restrict__ We,
                                                 const float* __restrict__ sim,
                                                 const int* __restrict__ nidx) {
    int blk = blockIdx.x;
    int t = threadIdx.x;
    if (blk < NHB) {
        // scatter
        __shared__ int cur[B_GR];
        if (t < B_GR) cur[t] = g_blockbase[blk * B_GR + t];
        __syncthreads();
        for (int e = blk * 256 + t; e < N_EDGES; e += NHB * 256) {
            int b = eb[e];
            int pos = atomicAdd(&cur[b], 1);
            g_eperm[pos] = e;
            g_edst[pos] = dst[e];
            g_ecoef[pos] = dist[src[e]];
        }
    } else if (blk < NHB + WSBLK) {
        // wsplit
        __shared__ float sim_s[B_GR * P];
        for (int i = t; i < B_GR * P; i += 256) sim_s[i] = sim[i];
        __syncthreads();
        int pos = (blk - NHB) * 256 + t;
        int n = pos >> 8, k = pos & 255;
        store_split(128, n, k, We[pos]);
        float wp[P];
#pragma unroll
        for (int p = 0; p < P; p++) wp[p] = Wnp[p * (D * D) + pos];
        for (int b = 0; b < B_GR; b++) {
            float a = 0.f;
#pragma unroll
            for (int p = 0; p < P; p++) a = fmaf(sim_s[b * P + p], wp[p], a);
            store_split(b, n, k, a);
        }
    } else {
        // plan (single block, 256 threads; per-b work on t < 128)
        __shared__ int cnts[B_GR];
        __shared__ int starts[B_GR];
        __shared__ int info[B_GR][2];  // elo, nlo
        int b = t;
        if (b < B_GR) {
            int elo = g_binstart[b], ecnt = g_binstart[b + 1] - elo;
            int nlo = lower_bound_dev(nidx, N_NODES, b);
            int ncnt = lower_bound_dev(nidx, N_NODES, b + 1) - nlo;
            cnts[b] = ((ecnt + 127) >> 7) + ((ncnt + 127) >> 7);
            info[b][0] = elo;
            info[b][1] = nlo;
        }
        __syncthreads();
        if (t == 0) {
            int run = 0;
            for (int i = 0; i < B_GR; i++) { starts[i] = run; run += cnts[i]; }
            g_ntiles = run;
        }
        __syncthreads();
        if (b < B_GR) {
            int elo = info[b][0], ecnt = g_binstart[b + 1] - elo;
            int nlo = info[b][1];
            int ncnt = lower_bound_dev(nidx, N_NODES, b + 1) - nlo;
            int et = (ecnt + 127) >> 7, nt = (ncnt + 127) >> 7;
            int idx = starts[b];
            for (int k = 0; k < et; k++)
                g_tiles[idx++] = make_int4(128, b, elo + k * 128, min(128, ecnt - k * 128));
            for (int k = 0; k < nt; k++)
                g_tiles[idx++] = make_int4(b, b, nlo + k * 128, min(128, ncnt - k * 128));
        }
    }
}

// ---------------- L3: main HMMA kernel (3-pass fp16, pass-split regs, 3 W bufs) ----------------
// 256 threads, 8 warps = 2 m-groups (64 rows) x 4 n-groups (32 cols of this half).
__global__ void __launch_bounds__(256, 2) main_kernel(const float* __restrict__ node_attrs,
                                                      const float* __restrict__ edge_attrs,
                                                      const float* __restrict__ instr,
                                                      const float* __restrict__ w_node,
                                                      const float* __restrict__ w_rel) {
    extern __shared__ char smem[];
    const int tb = blockIdx.x >> 1;
    if (tb >= g_ntiles) return;
    const int half = blockIdx.x & 1;
    const int nofs = half * 128;
    const int4 ti = g_tiles[tb];
    const bool isEdge = (ti.x == 128);
    const int tid = threadIdx.x;
    const int lane = tid & 31;
    const int wid = tid >> 5;
    const int mbase = (wid & 1) * 64;
    const int ngrp = wid >> 1;           // 0..3

    const uint32_t sb = smem_u32(smem);
    float* instr_s = (float*)(smem + OFF_INSTR);
    float* wvec_s = (float*)(smem + OFF_WVEC);
    float* red = (float*)(smem + OFF_RED);

    instr_s[tid] = instr[ti.y * D + tid];
    wvec_s[tid] = (isEdge ? w_rel : w_node)[tid];

    // A staging: 2 threads per row; thread covers 16 k-floats per chunk
    const int arow = tid >> 1;
    const int kseg = (tid & 1) * 16;
    const bool valid = arow < ti.w;
    const float* rowsrc = node_attrs;
    if (valid)
        rowsrc = isEdge ? edge_attrs + (size_t)g_eperm[ti.z + arow] * D
                        : node_attrs + (size_t)(ti.z + arow) * D;

    const __half* wh = g_Wsp + (size_t)ti.x * NCHUNK * W_CHUNK_ELEMS + (size_t)nofs * 32;

    float acc[4][4][4];
#pragma unroll
    for (int a = 0; a < 4; a++)
#pragma unroll
        for (int b = 0; b < 4; b++)
#pragma unroll
            for (int c = 0; c < 4; c++) acc[a][b][c] = 0.f;

    float4 va, vb, vc, vd;
#define ISSUE_W(c, buf)                                                             \
    do {                                                                            \
        uint32_t wbb = sb + OFF_W + (buf) * W_BUF_BYTES;                            \
        const __half* whc = wh + (size_t)(c) * W_CHUNK_ELEMS;                       \
        for (int s = tid; s < 512; s += 256) {                                      \
            int n_ = s >> 2, ks_ = s & 3;                                           \
            uint32_t d_ = wbb + n_ * 80 + ks_ * 16;                                 \
            size_t g_ = (size_t)n_ * 32 + ks_ * 8;                                  \
            cpasync16(d_, whc + g_);                                                \
            cpasync16(d_ + W_HL_BYTES, whc + WSP_HALF + g_);                        \
        }                                                                           \
        cp_commit();                                                                \
    } while (0)

#define LDG_A(c)                                                                    \
    do {                                                                            \
        if (valid) {                                                                \
            const float4* p_ = (const float4*)(rowsrc + (c) * KC + kseg);           \
            va = __ldg(p_); vb = __ldg(p_ + 1);                                     \
            vc = __ldg(p_ + 2); vd = __ldg(p_ + 3);                                 \
        } else {                                                                    \
            va = make_float4(0.f, 0.f, 0.f, 0.f);                                   \
            vb = va; vc = va; vd = va;                                              \
        }                                                                           \
    } while (0)

// Convert+store one float4 (4 halfs hi + 4 halfs lo), few live regs.
#define STS_ONE(v, ab_, off)                                                        \
    do {                                                                            \
        __half2 hA = __floats2half2_rn((v).x, (v).y);                               \
        __half2 hB = __floats2half2_rn((v).z, (v).w);                               \
        uint2 u_;                                                                   \
        u_.x = *(uint32_t*)&hA; u_.y = *(uint32_t*)&hB;                             \
        *(uint2*)((ab_) + (off)) = u_;                                              \
        __half2 lA = __floats2half2_rn((v).x - __half2float(__low2half(hA)),        \
                                       (v).y - __half2float(__high2half(hA)));     \
        __half2 lB = __floats2half2_rn((v).z - __half2float(__low2half(hB)),        \
                                       (v).w - __half2float(__high2half(hB)));     \
        u_.x = *(uint32_t*)&lA; u_.y = *(uint32_t*)&lB;                             \
        *(uint2*)((ab_) + A_HL_BYTES + (off)) = u_;                                 \
    } while (0)

#define STS_A(buf)                                                                  \
    do {                                                                            \
        char* ab_ = smem + OFF_A + (buf) * A_BUF_BYTES + arow * 80 + kseg * 2;      \
        STS_ONE(va, ab_, 0);                                                        \
        STS_ONE(vb, ab_, 8);                                                        \
        STS_ONE(vc, ab_, 16);                                                       \
        STS_ONE(vd, ab_, 24);                                                       \
    } while (0)

    // prologue: issue chunk 0 and 1 (buffers 0, 1), stage A chunk 0
    ISSUE_W(0, 0);
    LDG_A(0);
    STS_A(0);
    ISSUE_W(1, 1);

#pragma unroll 1
    for (int c = 0; c < NCHUNK; c++) {
        if (c == NCHUNK - 1) cp_wait_all(); else cp_wait_1();
        __syncthreads();
        // Safe 2-deep prefetch: buffer (c+2)%3 was last read in iteration c-1;
        // the barrier above proves all warps are past it.
        if (c + 2 < NCHUNK) ISSUE_W(c + 2, (c + 2) % 3);
        if (c + 1 < NCHUNK) LDG_A(c + 1);
        const int abuf = c & 1;
        const uint32_t abase = sb + OFF_A + abuf * A_BUF_BYTES;
        const uint32_t wbase = sb + OFF_W + (c % 3) * W_BUF_BYTES;
        // ---- pass group 1: Ah x (Wh, Wl) ----
#pragma unroll
        for (int ks = 0; ks < 2; ks++) {
            const int k0 = ks * 16;
            uint32_t ah[4][4];
#pragma unroll
            for (int mi = 0; mi < 4; mi++) {
                uint32_t ra = abase + (mbase + mi * 16 + (lane & 15)) * 80 + k0 * 2 + ((lane >> 4) * 16);
                ldsm4(ah[mi], ra);
            }
#pragma unroll
            for (int nip = 0; nip < 2; nip++) {
                const int nloc = ngrp * 32 + nip * 16;
                uint32_t rb = wbase + (nloc + ((lane >> 4) << 3) + (lane & 7)) * 80 + k0 * 2 +
                              (((lane >> 3) & 1) * 16);
                uint32_t bh[4], bl[4];
                ldsm4(bh, rb);
                ldsm4(bl, rb + W_HL_BYTES);
#pragma unroll
                for (int mi = 0; mi < 4; mi++) {
                    mma16816(acc[mi][nip * 2 + 0], ah[mi], bh[0], bh[1]);
                    mma16816(acc[mi][nip * 2 + 1], ah[mi], bh[2], bh[3]);
                    mma16816(acc[mi][nip * 2 + 0], ah[mi], bl[0], bl[1]);
                    mma16816(acc[mi][nip * 2 + 1], ah[mi], bl[2], bl[3]);
                }
            }
        }
        // ---- pass group 2: Al x Wh ----
#pragma unroll
        for (int ks = 0; ks < 2; ks++) {
            const int k0 = ks * 16;
            uint32_t al[4][4];
#pragma unroll
            for (int mi = 0; mi < 4; mi++) {
                uint32_t ra = abase + A_HL_BYTES + (mbase + mi * 16 + (lane & 15)) * 80 + k0 * 2 +
                              ((lane >> 4) * 16);
                ldsm4(al[mi], ra);
            }
#pragma unroll
            for (int nip = 0; nip < 2; nip++) {
                const int nloc = ngrp * 32 + nip * 16;
                uint32_t rb = wbase + (nloc + ((lane >> 4) << 3) + (lane & 7)) * 80 + k0 * 2 +
                              (((lane >> 3) & 1) * 16);
                uint32_t bh[4];
                ldsm4(bh, rb);
#pragma unroll
                for (int mi = 0; mi < 4; mi++) {
                    mma16816(acc[mi][nip * 2 + 0], al[mi], bh[0], bh[1]);
                    mma16816(acc[mi][nip * 2 + 1], al[mi], bh[2], bh[3]);
                }
            }
        }
        if (c + 1 < NCHUNK) STS_A(abuf ^ 1);
    }

    // ---- epilogue: per-row partial over this half's 128 columns ----
#pragma unroll
    for (int mi = 0; mi < 4; mi++) {
        float pr0 = 0.f, pr1 = 0.f;
#pragma unroll
        for (int ni = 0; ni < 4; ni++) {
            int c0 = nofs + ngrp * 32 + ni * 8 + (lane & 3) * 2;
            float w0 = wvec_s[c0], w1 = wvec_s[c0 + 1];
            float i0 = instr_s[c0], i1 = instr_s[c0 + 1];
            pr0 += w0 * elu1(i0 * acc[mi][ni][0]) + w1 * elu1(i1 * acc[mi][ni][1]);
            pr1 += w0 * elu1(i0 * acc[mi][ni][2]) + w1 * elu1(i1 * acc[mi][ni][3]);
        }
        pr0 += __shfl_xor_sync(0xFFFFFFFFu, pr0, 1);
        pr0 += __shfl_xor_sync(0xFFFFFFFFu, pr0, 2);
        pr1 += __shfl_xor_sync(0xFFFFFFFFu, pr1, 1);
        pr1 += __shfl_xor_sync(0xFFFFFFFFu, pr1, 2);
        if ((lane & 3) == 0) {
            int row = mbase + mi * 16 + (lane >> 2);
            red[row * 4 + ngrp] = pr0;
            red[(row + 8) * 4 + ngrp] = pr1;
        }
    }
    __syncthreads();
    if (tid < 128 && tid < ti.w) {
        float v = red[tid * 4] + red[tid * 4 + 1] + red[tid * 4 + 2] + red[tid * 4 + 3];
        int gl = ti.z + tid;
        if (isEdge) atomicAdd(&g_rel_logits[g_edst[gl]], g_ecoef[gl] * v);
        else atomicAdd(&g_state_logits[gl], v);
    }
#undef ISSUE_W
#undef LDG_A
#undef STS_ONE
#undef STS_A
}

// ---------------- L4: segment softmax + combine ----------------
__global__ void __launch_bounds__(256) softmax_kernel(const int* __restrict__ nidx,
                                                      const float* __restrict__ rel_sim,
                                                      float* __restrict__ out) {
    const int b = blockIdx.x;
    const int t = threadIdx.x;
    __shared__ float sh[256];
    __shared__ int bounds[2];
    if (t == 0) {
        bounds[0] = lower_bound_dev(nidx, N_NODES, b);
        bounds[1] = lower_bound_dev(nidx, N_NODES, b + 1);
    }
    __syncthreads();
    const int lo = bounds[0], hi = bounds[1];
    if (hi <= lo) return;

    float m1 = -1e30f, m2 = -1e30f;
    for (int i = lo + t; i < hi; i += 256) {
        m1 = fmaxf(m1, g_state_logits[i]);
        m2 = fmaxf(m2, g_rel_logits[i]);
    }
    sh[t] = m1; __syncthreads();
    for (int o = 128; o > 0; o >>= 1) { if (t < o) sh[t] = fmaxf(sh[t], sh[t + o]); __syncthreads(); }
    m1 = sh[0]; __syncthreads();
    sh[t] = m2; __syncthreads();
    for (int o = 128; o > 0; o >>= 1) { if (t < o) sh[t] = fmaxf(sh[t], sh[t + o]); __syncthreads(); }
    m2 = sh[0]; __syncthreads();

    float s1 = 0.f, s2 = 0.f;
    for (int i = lo + t; i < hi; i += 256) {
        s1 += expf(g_state_logits[i] - m1);
        s2 += expf(g_rel_logits[i] - m2);
    }
    sh[t] = s1; __syncthreads();
    for (int o = 128; o > 0; o >>= 1) { if (t < o) sh[t] += sh[t + o]; __syncthreads(); }
    s1 = sh[0]; __syncthreads();
    sh[t] = s2; __syncthreads();
    for (int o = 128; o > 0; o >>= 1) { if (t < o) sh[t] += sh[t + o]; __syncthreads(); }
    s2 = sh[0]; __syncthreads();

    const float r = rel_sim[b];
    const float inv1 = 1.f / s1, inv2 = 1.f / s2;
    for (int i = lo + t; i < hi; i += 256) {
        float ns = expf(g_state_logits[i] - m1) * inv1;
        float nr = expf(g_rel_logits[i] - m2) * inv2;
        out[i] = r * nr + (1.f - r) * ns;
    }
}

extern "C" void kernel_launch(void* const* d_in, const int* in_sizes, int n_in,
                              void* d_out, int out_size) {
    const float* instr        = (const float*)d_in[0];
    const float* distribution = (const float*)d_in[1];
    const float* sim          = (const float*)d_in[2];
    const float* rel_sim      = (const float*)d_in[3];
    const float* node_attrs   = (const float*)d_in[4];
    const float* edge_attrs   = (const float*)d_in[5];
    const float* Wnp          = (const float*)d_in[6];
    const float* We           = (const float*)d_in[7];
    const float* w_node       = (const float*)d_in[8];
    const float* w_rel        = (const float*)d_in[9];
    const int*   node_indices = (const int*)d_in[10];
    const int*   edge_batch   = (const int*)d_in[11];
    const int*   ei           = (const int*)d_in[12];
    float* out = (float*)d_out;

    cudaFuncSetAttribute(main_kernel, cudaFuncAttributeMaxDynamicSharedMemorySize, SMEM_NEED);

    l0_kernel<<<NHB + ZBLK, 256>>>(edge_batch);                       // launch 0
    scan_kernel<<<1, 128>>>();                                        // launch 1
    l2_kernel<<<NHB + WSBLK + 1, 256>>>(edge_batch, ei, ei + N_EDGES, // launch 2
                                        distribution, Wnp, We, sim, node_indices);
    main_kernel<<<2 * MAX_TILES, 256, SMEM_NEED>>>(node_attrs, edge_attrs,  // launch 3 (profiled)
                                                   instr, w_node, w_rel);
    softmax_kernel<<<B_GR, 256>>>(node_indices, rel_sim, out);        // launch 4
}